// round 7
// baseline (speedup 1.0000x reference)
#include <cuda_runtime.h>
#include <cstdint>
#include <math.h>
#include <mma.h>

using namespace nvcuda;

// ---------------------------------------------------------------------------
// Problem constants
// ---------------------------------------------------------------------------
#define NB     2
#define SEQ    2048
#define T_TOK  4096
#define DMODEL 1024
#define NH     16
#define HD     64
#define WINDOW 1024
#define NE     8
#define DFF    2048
#define CAP    512
#define OUT_MAIN (T_TOK * DMODEL)

// ---------------------------------------------------------------------------
// Scratch
// ---------------------------------------------------------------------------
__device__ float g_xn  [T_TOK * DMODEL];
__device__ float g_q   [T_TOK * DMODEL];
__device__ float g_k   [T_TOK * DMODEL];
__device__ float g_v   [T_TOK * DMODEL];
__device__ float g_ao  [T_TOK * DMODEL];
__device__ float g_h   [T_TOK * DMODEL];
__device__ float g_xn2 [T_TOK * DMODEL];
__device__ float g_wte [T_TOK * NE];
__device__ float g_hid [NE * CAP * 2 * DFF];
__device__ float g_act [NE * CAP * DFF];
__device__ int   g_capidx[NE * CAP];
__device__ float g_capval[NE * CAP];
__device__ float g_phis[NE];

// ---------------------------------------------------------------------------
// cp.async helpers
// ---------------------------------------------------------------------------
__device__ __forceinline__ void cp16(void* dst, const void* src)
{
    unsigned int d = (unsigned int)__cvta_generic_to_shared(dst);
    asm volatile("cp.async.cg.shared.global [%0], [%1], 16;\n" :: "r"(d), "l"(src));
}
__device__ __forceinline__ void cp_commit() { asm volatile("cp.async.commit_group;\n"); }
__device__ __forceinline__ void cp_wait1()  { asm volatile("cp.async.wait_group 1;\n"); }
__device__ __forceinline__ void cp_wait0()  { asm volatile("cp.async.wait_group 0;\n"); }

// mma.sync m16n8k8 tf32: D = A*B + D.  Operands as raw b32 (truncated tf32).
__device__ __forceinline__ void mma_tf32(float& d0, float& d1, float& d2, float& d3,
                                         unsigned a0, unsigned a1, unsigned a2, unsigned a3,
                                         unsigned b0, unsigned b1)
{
    asm volatile(
        "mma.sync.aligned.m16n8k8.row.col.f32.tf32.tf32.f32 "
        "{%0,%1,%2,%3},{%4,%5,%6,%7},{%8,%9},{%0,%1,%2,%3};\n"
        : "+f"(d0), "+f"(d1), "+f"(d2), "+f"(d3)
        : "r"(a0), "r"(a1), "r"(a2), "r"(a3), "r"(b0), "r"(b1));
}

// ---------------------------------------------------------------------------
// RMSNorm
// ---------------------------------------------------------------------------
__global__ void rmsnorm_kernel(const float* __restrict__ x,
                               const float* __restrict__ w,
                               float* __restrict__ o)
{
    int row = blockIdx.x;
    const float* xr = x + (long long)row * DMODEL;
    float vals[4];
    float ss = 0.f;
#pragma unroll
    for (int t = 0; t < 4; t++) {
        float v = xr[threadIdx.x + t * 256];
        vals[t] = v;
        ss += v * v;
    }
    __shared__ float red[8];
#pragma unroll
    for (int off = 16; off; off >>= 1)
        ss += __shfl_xor_sync(0xffffffffu, ss, off);
    if ((threadIdx.x & 31) == 0) red[threadIdx.x >> 5] = ss;
    __syncthreads();
    if (threadIdx.x == 0) {
        float s = 0.f;
#pragma unroll
        for (int i = 0; i < 8; i++) s += red[i];
        red[0] = s;
    }
    __syncthreads();
    float rinv = 1.f / sqrtf(red[0] / (float)DMODEL + 1e-6f);
    float* orow = o + (long long)row * DMODEL;
#pragma unroll
    for (int t = 0; t < 4; t++) {
        int d = threadIdx.x + t * 256;
        orow[d] = vals[t] * rinv * w[d];
    }
}

// ---------------------------------------------------------------------------
// WMMA tf32 GEMM (truncated tf32).
// CTA tile 256x128, BK=32, 256 threads, 8 warps each 64x64 (4x2 warp grid).
// EPI 0: plain. EPI 1: += resid. EPI 2: scatter atomicAdd * rowScale.
// EPI 3: fused QKV (B/C selected by blockIdx.x>>3).
// ---------------------------------------------------------------------------
#define BM 256
#define BN 128
#define ALD 36
#define BLD 132
#define STAGE_F (BM * ALD + 32 * BLD)      // 13440 floats
#define GEMM_SMEM_BYTES (2 * STAGE_F * 4)  // 107520 B

template<int EPI>
__global__ __launch_bounds__(256)
void wgemm_kernel(const float* __restrict__ A,
                  const float* __restrict__ B0,
                  const float* __restrict__ B1,
                  const float* __restrict__ B2,
                  float* __restrict__ C0,
                  float* __restrict__ C1,
                  float* __restrict__ C2,
                  const float* __restrict__ resid,
                  const int*  __restrict__ rowIdxA,
                  const int*  __restrict__ outIdx,
                  const float* __restrict__ rowScale,
                  int N, int K,
                  long long aB, long long bB, long long cB, int idxB)
{
    extern __shared__ float sm[];
    __shared__ int   idx_sm[BM];
    __shared__ float scl_sm[BM];

    int e = blockIdx.z;
    const float* A_ = A + (long long)e * aB;
    const float* B_;
    float* C_;
    int colBase;
    if (EPI == 3) {
        int sel = blockIdx.x >> 3;
        colBase = (blockIdx.x & 7) * BN;
        B_ = (sel == 0) ? B0 : (sel == 1) ? B1 : B2;
        C_ = (sel == 0) ? C0 : (sel == 1) ? C1 : C2;
    } else {
        colBase = blockIdx.x * BN;
        B_ = B0 + (long long)e * bB;
        C_ = C0 + (long long)e * cB;
    }

    int tid = threadIdx.x;
    int w   = tid >> 5;
    int wr  = w >> 1;         // 0..3  (64-row band)
    int wc  = w & 1;          // 0..1  (64-col band)
    int rowBase = blockIdx.y * BM;

    {
        int ar = rowBase + tid;
        idx_sm[tid] = (EPI == 0 && rowIdxA) ? rowIdxA[e * idxB + ar] : ar;
        if (EPI == 2) {
            scl_sm[tid] = rowScale[e * idxB + ar];
            idx_sm[tid] = outIdx[e * idxB + ar];   // scatter target rows
        }
    }
    __syncthreads();

    wmma::fragment<wmma::accumulator, 16, 16, 8, float> acc[4][4];
#pragma unroll
    for (int i = 0; i < 4; i++)
#pragma unroll
        for (int j = 0; j < 4; j++) wmma::fill_fragment(acc[i][j], 0.f);

    int nIt = K >> 5;

    auto load_tile = [&](int it, int buf) {
        float* As = sm + buf * STAGE_F;
        float* Bs = As + BM * ALD;
        int k0 = it << 5;
#pragma unroll
        for (int t = 0; t < 8; t++) {
            int g  = tid + t * 256;
            int m  = g >> 3;
            int kq = (g & 7) << 2;
            long long arow = (EPI == 2) ? (long long)(rowBase + m) : (long long)idx_sm[m];
            cp16(As + m * ALD + kq, A_ + arow * K + k0 + kq);
        }
#pragma unroll
        for (int t = 0; t < 4; t++) {
            int g  = tid + t * 256;
            int kk = g >> 5;
            int nq = (g & 31) << 2;
            cp16(Bs + kk * BLD + nq, B_ + (long long)(k0 + kk) * N + colBase + nq);
        }
        cp_commit();
    };

    load_tile(0, 0);
    for (int it = 0; it < nIt; it++) {
        if (it + 1 < nIt) { load_tile(it + 1, (it + 1) & 1); cp_wait1(); }
        else cp_wait0();
        __syncthreads();

        float* As = sm + (it & 1) * STAGE_F;
        float* Bs = As + BM * ALD;
#pragma unroll
        for (int ks = 0; ks < 4; ks++) {
            wmma::fragment<wmma::matrix_a, 16, 16, 8, wmma::precision::tf32, wmma::row_major> a[4];
            wmma::fragment<wmma::matrix_b, 16, 16, 8, wmma::precision::tf32, wmma::row_major> b[4];
#pragma unroll
            for (int i = 0; i < 4; i++)
                wmma::load_matrix_sync(a[i], As + (wr * 64 + i * 16) * ALD + ks * 8, ALD);
#pragma unroll
            for (int j = 0; j < 4; j++)
                wmma::load_matrix_sync(b[j], Bs + (ks * 8) * BLD + wc * 64 + j * 16, BLD);
#pragma unroll
            for (int i = 0; i < 4; i++)
#pragma unroll
                for (int j = 0; j < 4; j++)
                    wmma::mma_sync(acc[i][j], a[i], b[j], acc[i][j]);
        }
        __syncthreads();
    }

    if (EPI == 0 || EPI == 3) {
#pragma unroll
        for (int i = 0; i < 4; i++)
#pragma unroll
            for (int j = 0; j < 4; j++) {
                long long m = rowBase + wr * 64 + i * 16;
                long long n = colBase + wc * 64 + j * 16;
                wmma::store_matrix_sync(C_ + m * N + n, acc[i][j], N, wmma::mem_row_major);
            }
    } else {
        float* Csm = sm;   // 128 x 132 staging, two halves
#pragma unroll
        for (int half = 0; half < 2; half++) {
            if ((wr >> 1) == half) {
#pragma unroll
                for (int i = 0; i < 4; i++)
#pragma unroll
                    for (int j = 0; j < 4; j++)
                        wmma::store_matrix_sync(Csm + ((wr & 1) * 64 + i * 16) * BLD + wc * 64 + j * 16,
                                                acc[i][j], BLD, wmma::mem_row_major);
            }
            __syncthreads();
#pragma unroll
            for (int t = 0; t < 64; t++) {
                int idx = tid + t * 256;
                int m = idx >> 7, n = idx & 127;
                int gmRow = rowBase + half * 128 + m;
                if (EPI == 1) {
                    long long gm = (long long)gmRow * N + colBase + n;
                    C_[gm] = Csm[m * BLD + n] + resid[gm];
                } else { // EPI 2
                    atomicAdd(&C_[(long long)idx_sm[half * 128 + m] * N + colBase + n],
                              Csm[m * BLD + n] * scl_sm[half * 128 + m]);
                }
            }
            __syncthreads();
        }
    }
}

// ---------------------------------------------------------------------------
// RoPE
// ---------------------------------------------------------------------------
__global__ void rope_kernel(float* __restrict__ q, float* __restrict__ k)
{
    int idx = blockIdx.x * blockDim.x + threadIdx.x;
    if (idx >= T_TOK * NH * (HD / 2)) return;
    int j   = idx & 31;
    int hh  = (idx >> 5) & 15;
    int row = idx >> 9;
    int s   = row & (SEQ - 1);

    float inv = (float)(1.0 / pow(10000.0, (double)j / 32.0));
    float ang = (float)s * inv;
    float c = cosf(ang), sn = sinf(ang);

    long long base = (long long)row * DMODEL + hh * HD;
    float q1 = q[base + j], q2 = q[base + j + 32];
    q[base + j]      = q1 * c - q2 * sn;
    q[base + j + 32] = q2 * c + q1 * sn;
    float k1 = k[base + j], k2 = k[base + j + 32];
    k[base + j]      = k1 * c - k2 * sn;
    k[base + j + 32] = k2 * c + k1 * sn;
}

// ---------------------------------------------------------------------------
// FA2-style flash attention on raw mma.sync m16n8k8 tf32.
// Block: 128 q-rows, 8 warps (16 rows/warp), K/V tiles of 64 keys cp.async
// double-buffered in smem. S and O accumulators live in registers.
// ---------------------------------------------------------------------------
#define KLD 68            // K tile ld (floats): bank=(4g+t) unique
#define VLD 72            // V tile ld (floats): bank=(8t+g) unique
#define KV_STAGE_F (64 * KLD + 64 * VLD)          // 8960 floats per stage
#define ATT_SMEM_BYTES (2 * KV_STAGE_F * 4)       // 71680 B

__global__ __launch_bounds__(256, 2)
void attn_kernel(const float* __restrict__ q,
                 const float* __restrict__ k,
                 const float* __restrict__ v,
                 float* __restrict__ o)
{
    extern __shared__ float sm[];

    int qt = blockIdx.x, h = blockIdx.y, b = blockIdx.z;
    int i0 = qt * 128;
    int tid  = threadIdx.x;
    int w    = tid >> 5;
    int lane = tid & 31;
    int g    = lane >> 2;      // groupID 0..7
    int t    = lane & 3;       // threadID in group 0..3
    long long base = ((long long)b * SEQ) * DMODEL + h * HD;

    int r0 = i0 + w * 16 + g;  // global seq row (first)
    int r1 = r0 + 8;           // second row

    // Q A-fragments in registers (scaled)
    unsigned qa[8][4];
#pragma unroll
    for (int kc = 0; kc < 8; kc++) {
        qa[kc][0] = __float_as_uint(q[base + (long long)r0 * DMODEL + kc * 8 + t]     * 0.125f);
        qa[kc][1] = __float_as_uint(q[base + (long long)r1 * DMODEL + kc * 8 + t]     * 0.125f);
        qa[kc][2] = __float_as_uint(q[base + (long long)r0 * DMODEL + kc * 8 + t + 4] * 0.125f);
        qa[kc][3] = __float_as_uint(q[base + (long long)r1 * DMODEL + kc * 8 + t + 4] * 0.125f);
    }

    float m0 = -1e30f, m1 = -1e30f, l0 = 0.f, l1 = 0.f;
    float oacc[8][4];
#pragma unroll
    for (int nb = 0; nb < 8; nb++)
#pragma unroll
        for (int u = 0; u < 4; u++) oacc[nb][u] = 0.f;

    int jstart = i0 - (WINDOW - 1); if (jstart < 0) jstart = 0;
    int jt0 = jstart >> 6;
    int jt1 = (i0 + 127) >> 6;
    int nTiles = jt1 - jt0 + 1;

    auto loadKV = [&](int jt, int stage) {
        float* Ks = sm + stage * KV_STAGE_F;
        float* Vs = Ks + 64 * KLD;
        int j0 = jt << 6;
#pragma unroll
        for (int u = 0; u < 4; u++) {
            int gidx = tid + u * 256;          // 0..1023
            int row  = gidx >> 4;              // 0..63
            int c4   = (gidx & 15) << 2;       // 0..60
            long long gp = base + (long long)(j0 + row) * DMODEL + c4;
            cp16(Ks + row * KLD + c4, k + gp);
            cp16(Vs + row * VLD + c4, v + gp);
        }
        cp_commit();
    };

    loadKV(jt0, 0);
    for (int it = 0; it < nTiles; it++) {
        int j0 = (jt0 + it) << 6;
        if (it + 1 < nTiles) { loadKV(jt0 + it + 1, (it + 1) & 1); cp_wait1(); }
        else cp_wait0();
        __syncthreads();

        float* Ks = sm + (it & 1) * KV_STAGE_F;
        float* Vs = Ks + 64 * KLD;

        // ---- S = Q @ K^T (registers) ----
        float sc[8][4];
#pragma unroll
        for (int kb = 0; kb < 8; kb++) {
            float d0 = 0.f, d1 = 0.f, d2 = 0.f, d3 = 0.f;
            const float* krow = Ks + (kb * 8 + g) * KLD;
#pragma unroll
            for (int kc = 0; kc < 8; kc++) {
                unsigned b0 = __float_as_uint(krow[kc * 8 + t]);
                unsigned b1 = __float_as_uint(krow[kc * 8 + t + 4]);
                mma_tf32(d0, d1, d2, d3, qa[kc][0], qa[kc][1], qa[kc][2], qa[kc][3], b0, b1);
            }
            sc[kb][0] = d0; sc[kb][1] = d1; sc[kb][2] = d2; sc[kb][3] = d3;
        }

        // ---- masked online softmax (registers) ----
        float tm0 = -1e30f, tm1 = -1e30f;
#pragma unroll
        for (int kb = 0; kb < 8; kb++) {
            int c0 = j0 + kb * 8 + 2 * t;
            int c1 = c0 + 1;
            int d00 = r0 - c0, d01 = r0 - c1, d10 = r1 - c0, d11 = r1 - c1;
            if (d00 >= 0 && d00 < WINDOW) tm0 = fmaxf(tm0, sc[kb][0]);
            if (d01 >= 0 && d01 < WINDOW) tm0 = fmaxf(tm0, sc[kb][1]);
            if (d10 >= 0 && d10 < WINDOW) tm1 = fmaxf(tm1, sc[kb][2]);
            if (d11 >= 0 && d11 < WINDOW) tm1 = fmaxf(tm1, sc[kb][3]);
        }
        tm0 = fmaxf(tm0, __shfl_xor_sync(0xffffffffu, tm0, 1));
        tm0 = fmaxf(tm0, __shfl_xor_sync(0xffffffffu, tm0, 2));
        tm1 = fmaxf(tm1, __shfl_xor_sync(0xffffffffu, tm1, 1));
        tm1 = fmaxf(tm1, __shfl_xor_sync(0xffffffffu, tm1, 2));

        float mn0 = fmaxf(m0, tm0);
        float mn1 = fmaxf(m1, tm1);
        float alpha0 = __expf(m0 - mn0);
        float alpha1 = __expf(m1 - mn1);
        m0 = mn0; m1 = mn1;

        float sum0 = 0.f, sum1 = 0.f;
#pragma unroll
        for (int kb = 0; kb < 8; kb++) {
            int c0 = j0 + kb * 8 + 2 * t;
            int c1 = c0 + 1;
            int d00 = r0 - c0, d01 = r0 - c1, d10 = r1 - c0, d11 = r1 - c1;
            float p00 = (d00 >= 0 && d00 < WINDOW) ? __expf(sc[kb][0] - mn0) : 0.f;
            float p01 = (d01 >= 0 && d01 < WINDOW) ? __expf(sc[kb][1] - mn0) : 0.f;
            float p10 = (d10 >= 0 && d10 < WINDOW) ? __expf(sc[kb][2] - mn1) : 0.f;
            float p11 = (d11 >= 0 && d11 < WINDOW) ? __expf(sc[kb][3] - mn1) : 0.f;
            sc[kb][0] = p00; sc[kb][1] = p01; sc[kb][2] = p10; sc[kb][3] = p11;
            sum0 += p00 + p01;
            sum1 += p10 + p11;
        }
        sum0 += __shfl_xor_sync(0xffffffffu, sum0, 1);
        sum0 += __shfl_xor_sync(0xffffffffu, sum0, 2);
        sum1 += __shfl_xor_sync(0xffffffffu, sum1, 1);
        sum1 += __shfl_xor_sync(0xffffffffu, sum1, 2);
        l0 = l0 * alpha0 + sum0;
        l1 = l1 * alpha1 + sum1;

        // scale O accumulators
#pragma unroll
        for (int nb = 0; nb < 8; nb++) {
            oacc[nb][0] *= alpha0; oacc[nb][1] *= alpha0;
            oacc[nb][2] *= alpha1; oacc[nb][3] *= alpha1;
        }

        // ---- O += P @ V ----
        int srcA = (lane & ~3) | (t >> 1);
        int srcB = srcA + 2;
#pragma unroll
        for (int kb = 0; kb < 8; kb++) {
            // convert P (C layout, cols 2t/2t+1) -> A operand (cols t, t+4)
            float v0, v1;
            v0 = __shfl_sync(0xffffffffu, sc[kb][0], srcA);
            v1 = __shfl_sync(0xffffffffu, sc[kb][1], srcA);
            unsigned pa0 = __float_as_uint((t & 1) ? v1 : v0);
            v0 = __shfl_sync(0xffffffffu, sc[kb][2], srcA);
            v1 = __shfl_sync(0xffffffffu, sc[kb][3], srcA);
            unsigned pa1 = __float_as_uint((t & 1) ? v1 : v0);
            v0 = __shfl_sync(0xffffffffu, sc[kb][0], srcB);
            v1 = __shfl_sync(0xffffffffu, sc[kb][1], srcB);
            unsigned pa2 = __float_as_uint((t & 1) ? v1 : v0);
            v0 = __shfl_sync(0xffffffffu, sc[kb][2], srcB);
            v1 = __shfl_sync(0xffffffffu, sc[kb][3], srcB);
            unsigned pa3 = __float_as_uint((t & 1) ? v1 : v0);

            const float* vrow0 = Vs + (kb * 8 + t) * VLD;
            const float* vrow1 = Vs + (kb * 8 + t + 4) * VLD;
#pragma unroll
            for (int nb = 0; nb < 8; nb++) {
                unsigned b0 = __float_as_uint(vrow0[nb * 8 + g]);
                unsigned b1 = __float_as_uint(vrow1[nb * 8 + g]);
                mma_tf32(oacc[nb][0], oacc[nb][1], oacc[nb][2], oacc[nb][3],
                         pa0, pa1, pa2, pa3, b0, b1);
            }
        }
        __syncthreads();
    }

    // ---- write normalized output ----
    float rl0 = 1.f / l0;
    float rl1 = 1.f / l1;
#pragma unroll
    for (int nb = 0; nb < 8; nb++) {
        float2 o0 = make_float2(oacc[nb][0] * rl0, oacc[nb][1] * rl0);
        float2 o1 = make_float2(oacc[nb][2] * rl1, oacc[nb][3] * rl1);
        *(float2*)(o + base + (long long)r0 * DMODEL + nb * 8 + 2 * t) = o0;
        *(float2*)(o + base + (long long)r1 * DMODEL + nb * 8 + 2 * t) = o1;
    }
}

// ---------------------------------------------------------------------------
// Gating
// ---------------------------------------------------------------------------
__global__ void gate_kernel(const float* __restrict__ xn2,
                            const float* __restrict__ gw,
                            float* __restrict__ wte,
                            float* __restrict__ phis)
{
    int tok  = (blockIdx.x * blockDim.x + threadIdx.x) >> 5;
    int lane = threadIdx.x & 31;
    if (tok >= T_TOK) return;
    const float* xr = xn2 + (long long)tok * DMODEL;
    float acc[NE];
#pragma unroll
    for (int e = 0; e < NE; e++) acc[e] = 0.f;
    for (int d = lane; d < DMODEL; d += 32) {
        float xv = xr[d];
        const float* g = gw + d * NE;
#pragma unroll
        for (int e = 0; e < NE; e++) acc[e] = fmaf(xv, g[e], acc[e]);
    }
#pragma unroll
    for (int e = 0; e < NE; e++)
#pragma unroll
        for (int off = 16; off; off >>= 1)
            acc[e] += __shfl_xor_sync(0xffffffffu, acc[e], off);

    if (lane == 0) {
        float mx = acc[0];
#pragma unroll
        for (int e = 1; e < NE; e++) mx = fmaxf(mx, acc[e]);
        float p[NE], s = 0.f;
#pragma unroll
        for (int e = 0; e < NE; e++) { p[e] = expf(acc[e] - mx); s += p[e]; }
#pragma unroll
        for (int e = 0; e < NE; e++) p[e] /= s;
        int i1 = 0;
#pragma unroll
        for (int e = 1; e < NE; e++) if (p[e] > p[i1]) i1 = e;
        int i2 = -1;
#pragma unroll
        for (int e = 0; e < NE; e++)
            if (e != i1 && (i2 < 0 || p[e] > p[i2])) i2 = e;
#pragma unroll
        for (int e = 0; e < NE; e++)
            wte[(long long)tok * NE + e] = (e == i1) ? p[i1] : (e == i2) ? p[i2] : 0.f;
#pragma unroll
        for (int e = 0; e < NE; e++) atomicAdd(&phis[e], p[e]);
    }
}

// ---------------------------------------------------------------------------
// Per-expert top-CAP selection (bitonic, stable)
// ---------------------------------------------------------------------------
__global__ void expert_topk_kernel(const float* __restrict__ wte,
                                   int* __restrict__ capidx,
                                   float* __restrict__ capval)
{
    __shared__ float sv[T_TOK];
    __shared__ int   si[T_TOK];
    int e = blockIdx.x;
    for (int i = threadIdx.x; i < T_TOK; i += 1024) {
        sv[i] = wte[(long long)i * NE + e];
        si[i] = i;
    }
    __syncthreads();
    for (int kk = 2; kk <= T_TOK; kk <<= 1) {
        for (int j = kk >> 1; j > 0; j >>= 1) {
            for (int i = threadIdx.x; i < T_TOK; i += 1024) {
                int l = i ^ j;
                if (l > i) {
                    bool dir = ((i & kk) == 0);
                    float vi = sv[i], vl = sv[l];
                    int   xi = si[i], xl = si[l];
                    bool before = (vi > vl) || (vi == vl && xi < xl);
                    if (before != dir) {
                        sv[i] = vl; sv[l] = vi;
                        si[i] = xl; si[l] = xi;
                    }
                }
            }
            __syncthreads();
        }
    }
    for (int i = threadIdx.x; i < CAP; i += 1024) {
        capidx[e * CAP + i] = si[i];
        capval[e * CAP + i] = sv[i];
    }
}

// ---------------------------------------------------------------------------
// SwiGLU
// ---------------------------------------------------------------------------
__global__ void act_kernel(const float* __restrict__ hid, float* __restrict__ act)
{
    long long idx = (long long)blockIdx.x * blockDim.x + threadIdx.x;
    if (idx >= (long long)NE * CAP * DFF) return;
    int f = (int)(idx % DFF);
    long long row = idx / DFF;
    long long hbase = row * (2 * DFF);
    float h1 = hid[hbase + f];
    float h2 = hid[hbase + DFF + f];
    act[idx] = h1 * (h2 / (1.f + expf(-h2)));
}

// ---------------------------------------------------------------------------
// Utility
// ---------------------------------------------------------------------------
__global__ void zero_phis_kernel(float* __restrict__ phis)
{
    if (threadIdx.x < NE) phis[threadIdx.x] = 0.f;
}

__global__ void copy_kernel(const float* __restrict__ src, float* __restrict__ dst)
{
    long long idx = (long long)blockIdx.x * blockDim.x + threadIdx.x;
    if (idx < (long long)(OUT_MAIN / 4)) {
        ((float4*)dst)[idx] = ((const float4*)src)[idx];
    }
}

__global__ void aux_kernel(const float* __restrict__ phis, float* __restrict__ out, int out_size)
{
    if (out_size > OUT_MAIN) {
        float s = 0.f;
#pragma unroll
        for (int e = 0; e < NE; e++) {
            float pm = phis[e] / (float)T_TOK;
            s += pm * pm;
        }
        out[OUT_MAIN] = (float)NE * s;
    }
}

// ---------------------------------------------------------------------------
// Launch
// ---------------------------------------------------------------------------
extern "C" void kernel_launch(void* const* d_in, const int* in_sizes, int n_in,
                              void* d_out, int out_size)
{
    const float* x   = (const float*)d_in[0];
    const float* wq  = (const float*)d_in[1];
    const float* wk  = (const float*)d_in[2];
    const float* wv  = (const float*)d_in[3];
    const float* wo  = (const float*)d_in[4];
    const float* n1w = (const float*)d_in[5];
    const float* n2w = (const float*)d_in[6];
    const float* gw  = (const float*)d_in[7];
    const float* w1  = (const float*)d_in[8];
    const float* w2  = (const float*)d_in[9];
    float* out = (float*)d_out;

    float *xn, *qb, *kb, *vb, *ao, *hb, *xn2, *wte, *hid, *act, *capv, *phis;
    int* capi;
    cudaGetSymbolAddress((void**)&xn,  g_xn);
    cudaGetSymbolAddress((void**)&qb,  g_q);
    cudaGetSymbolAddress((void**)&kb,  g_k);
    cudaGetSymbolAddress((void**)&vb,  g_v);
    cudaGetSymbolAddress((void**)&ao,  g_ao);
    cudaGetSymbolAddress((void**)&hb,  g_h);
    cudaGetSymbolAddress((void**)&xn2, g_xn2);
    cudaGetSymbolAddress((void**)&wte, g_wte);
    cudaGetSymbolAddress((void**)&hid, g_hid);
    cudaGetSymbolAddress((void**)&act, g_act);
    cudaGetSymbolAddress((void**)&capi, g_capidx);
    cudaGetSymbolAddress((void**)&capv, g_capval);
    cudaGetSymbolAddress((void**)&phis, g_phis);

    static int attr_done = 0;
    if (!attr_done) {
        cudaFuncSetAttribute(wgemm_kernel<0>, cudaFuncAttributeMaxDynamicSharedMemorySize, GEMM_SMEM_BYTES);
        cudaFuncSetAttribute(wgemm_kernel<1>, cudaFuncAttributeMaxDynamicSharedMemorySize, GEMM_SMEM_BYTES);
        cudaFuncSetAttribute(wgemm_kernel<2>, cudaFuncAttributeMaxDynamicSharedMemorySize, GEMM_SMEM_BYTES);
        cudaFuncSetAttribute(wgemm_kernel<3>, cudaFuncAttributeMaxDynamicSharedMemorySize, GEMM_SMEM_BYTES);
        cudaFuncSetAttribute(attn_kernel, cudaFuncAttributeMaxDynamicSharedMemorySize, ATT_SMEM_BYTES);
        attr_done = 1;
    }

    // ---- sublayer 1 ----
    rmsnorm_kernel<<<T_TOK, 256>>>(x, n1w, xn);

    // Fused QKV: grid.x = 3 weights x 8 col-blocks, grid.y = 4096/256
    wgemm_kernel<3><<<dim3(24, T_TOK / BM, 1), 256, GEMM_SMEM_BYTES>>>(
        xn, wq, wk, wv, qb, kb, vb, nullptr, nullptr, nullptr, nullptr,
        DMODEL, DMODEL, 0, 0, 0, 0);

    rope_kernel<<<(T_TOK * NH * 32 + 255) / 256, 256>>>(qb, kb);

    attn_kernel<<<dim3(SEQ / 128, NH, NB), 256, ATT_SMEM_BYTES>>>(qb, kb, vb, ao);

    wgemm_kernel<1><<<dim3(DMODEL / BN, T_TOK / BM, 1), 256, GEMM_SMEM_BYTES>>>(
        ao, wo, nullptr, nullptr, hb, nullptr, nullptr, x, nullptr, nullptr, nullptr,
        DMODEL, DMODEL, 0, 0, 0, 0);

    // ---- sublayer 2: MoE ----
    rmsnorm_kernel<<<T_TOK, 256>>>(hb, n2w, xn2);

    zero_phis_kernel<<<1, 32>>>(phis);
    gate_kernel<<<(T_TOK * 32) / 256, 256>>>(xn2, gw, wte, phis);
    expert_topk_kernel<<<NE, 1024>>>(wte, capi, capv);

    // hidden[e] = xn2[capidx[e]] @ w1[e]   (M=512, N=4096, K=1024)
    wgemm_kernel<0><<<dim3((2 * DFF) / BN, CAP / BM, NE), 256, GEMM_SMEM_BYTES>>>(
        xn2, w1, nullptr, nullptr, hid, nullptr, nullptr, nullptr, capi, nullptr, nullptr,
        2 * DFF, DMODEL,
        0, (long long)DMODEL * 2 * DFF, (long long)CAP * 2 * DFF, CAP);

    act_kernel<<<(NE * CAP * DFF + 255) / 256, 256>>>(hid, act);

    copy_kernel<<<(OUT_MAIN / 4 + 255) / 256, 256>>>(hb, out);

    // out[capidx[e][c]] += (act[e] @ w2[e])[c] * capval[e][c]  (M=512,N=1024,K=2048)
    wgemm_kernel<2><<<dim3(DMODEL / BN, CAP / BM, NE), 256, GEMM_SMEM_BYTES>>>(
        act, w2, nullptr, nullptr, out, nullptr, nullptr, nullptr, nullptr, capi, capv,
        DMODEL, DFF,
        (long long)CAP * DFF, (long long)DFF * DMODEL, 0, CAP);

    aux_kernel<<<1, 1>>>(phis, out, out_size);

    (void)in_sizes; (void)n_in;
}

// round 10
// speedup vs baseline: 1.7896x; 1.7896x over previous
#include <cuda_runtime.h>
#include <cstdint>
#include <math.h>
#include <mma.h>

using namespace nvcuda;

// ---------------------------------------------------------------------------
// Problem constants
// ---------------------------------------------------------------------------
#define NB     2
#define SEQ    2048
#define T_TOK  4096
#define DMODEL 1024
#define NH     16
#define HD     64
#define WINDOW 1024
#define NE     8
#define DFF    2048
#define CAP    512
#define OUT_MAIN (T_TOK * DMODEL)

// ---------------------------------------------------------------------------
// Scratch
// ---------------------------------------------------------------------------
__device__ float g_xn  [T_TOK * DMODEL];
__device__ float g_q   [T_TOK * DMODEL];
__device__ float g_k   [T_TOK * DMODEL];
__device__ float g_v   [T_TOK * DMODEL];
__device__ float g_ao  [T_TOK * DMODEL];
__device__ float g_h   [T_TOK * DMODEL];
__device__ float g_xn2 [T_TOK * DMODEL];
__device__ float g_wte [T_TOK * NE];
__device__ float g_hid [NE * CAP * 2 * DFF];
__device__ float g_act [NE * CAP * DFF];
__device__ int   g_capidx[NE * CAP];
__device__ float g_capval[NE * CAP];
__device__ float g_phis[NE];

// ---------------------------------------------------------------------------
// cp.async helpers
// ---------------------------------------------------------------------------
__device__ __forceinline__ void cp16(void* dst, const void* src)
{
    unsigned int d = (unsigned int)__cvta_generic_to_shared(dst);
    asm volatile("cp.async.cg.shared.global [%0], [%1], 16;\n" :: "r"(d), "l"(src));
}
__device__ __forceinline__ void cp_commit() { asm volatile("cp.async.commit_group;\n"); }
__device__ __forceinline__ void cp_wait1()  { asm volatile("cp.async.wait_group 1;\n"); }
__device__ __forceinline__ void cp_wait0()  { asm volatile("cp.async.wait_group 0;\n"); }

// mma.sync m16n8k8 tf32: D = A*B + D.  Operands as raw b32 (truncated tf32).
__device__ __forceinline__ void mma_tf32(float& d0, float& d1, float& d2, float& d3,
                                         unsigned a0, unsigned a1, unsigned a2, unsigned a3,
                                         unsigned b0, unsigned b1)
{
    asm volatile(
        "mma.sync.aligned.m16n8k8.row.col.f32.tf32.tf32.f32 "
        "{%0,%1,%2,%3},{%4,%5,%6,%7},{%8,%9},{%0,%1,%2,%3};\n"
        : "+f"(d0), "+f"(d1), "+f"(d2), "+f"(d3)
        : "r"(a0), "r"(a1), "r"(a2), "r"(a3), "r"(b0), "r"(b1));
}

// ---------------------------------------------------------------------------
// RMSNorm
// ---------------------------------------------------------------------------
__global__ void rmsnorm_kernel(const float* __restrict__ x,
                               const float* __restrict__ w,
                               float* __restrict__ o)
{
    int row = blockIdx.x;
    const float* xr = x + (long long)row * DMODEL;
    float vals[4];
    float ss = 0.f;
#pragma unroll
    for (int t = 0; t < 4; t++) {
        float v = xr[threadIdx.x + t * 256];
        vals[t] = v;
        ss += v * v;
    }
    __shared__ float red[8];
#pragma unroll
    for (int off = 16; off; off >>= 1)
        ss += __shfl_xor_sync(0xffffffffu, ss, off);
    if ((threadIdx.x & 31) == 0) red[threadIdx.x >> 5] = ss;
    __syncthreads();
    if (threadIdx.x == 0) {
        float s = 0.f;
#pragma unroll
        for (int i = 0; i < 8; i++) s += red[i];
        red[0] = s;
    }
    __syncthreads();
    float rinv = 1.f / sqrtf(red[0] / (float)DMODEL + 1e-6f);
    float* orow = o + (long long)row * DMODEL;
#pragma unroll
    for (int t = 0; t < 4; t++) {
        int d = threadIdx.x + t * 256;
        orow[d] = vals[t] * rinv * w[d];
    }
}

// ---------------------------------------------------------------------------
// WMMA tf32 GEMM (truncated tf32).
// CTA tile 256x128, BK=32, 256 threads, 8 warps each 64x64 (4x2 warp grid).
// EPI 0: plain. EPI 1: += resid, dual-store (C0 and C1 if non-null).
// EPI 2: scatter atomicAdd * rowScale. EPI 3: fused QKV.
// ---------------------------------------------------------------------------
#define BM 256
#define BN 128
#define ALD 36
#define BLD 132
#define STAGE_F (BM * ALD + 32 * BLD)      // 13440 floats
#define GEMM_SMEM_BYTES (2 * STAGE_F * 4)  // 107520 B

template<int EPI>
__global__ __launch_bounds__(256)
void wgemm_kernel(const float* __restrict__ A,
                  const float* __restrict__ B0,
                  const float* __restrict__ B1,
                  const float* __restrict__ B2,
                  float* __restrict__ C0,
                  float* __restrict__ C1,
                  float* __restrict__ C2,
                  const float* __restrict__ resid,
                  const int*  __restrict__ rowIdxA,
                  const int*  __restrict__ outIdx,
                  const float* __restrict__ rowScale,
                  int N, int K,
                  long long aB, long long bB, long long cB, int idxB)
{
    extern __shared__ float sm[];
    __shared__ int   idx_sm[BM];
    __shared__ float scl_sm[BM];

    int e = blockIdx.z;
    const float* A_ = A + (long long)e * aB;
    const float* B_;
    float* C_;
    int colBase;
    if (EPI == 3) {
        int sel = blockIdx.x >> 3;
        colBase = (blockIdx.x & 7) * BN;
        B_ = (sel == 0) ? B0 : (sel == 1) ? B1 : B2;
        C_ = (sel == 0) ? C0 : (sel == 1) ? C1 : C2;
    } else {
        colBase = blockIdx.x * BN;
        B_ = B0 + (long long)e * bB;
        C_ = C0 + (long long)e * cB;
    }

    int tid = threadIdx.x;
    int w   = tid >> 5;
    int wr  = w >> 1;         // 0..3  (64-row band)
    int wc  = w & 1;          // 0..1  (64-col band)
    int rowBase = blockIdx.y * BM;

    {
        int ar = rowBase + tid;
        idx_sm[tid] = (EPI == 0 && rowIdxA) ? rowIdxA[e * idxB + ar] : ar;
        if (EPI == 2) {
            scl_sm[tid] = rowScale[e * idxB + ar];
            idx_sm[tid] = outIdx[e * idxB + ar];   // scatter target rows
        }
    }
    __syncthreads();

    wmma::fragment<wmma::accumulator, 16, 16, 8, float> acc[4][4];
#pragma unroll
    for (int i = 0; i < 4; i++)
#pragma unroll
        for (int j = 0; j < 4; j++) wmma::fill_fragment(acc[i][j], 0.f);

    int nIt = K >> 5;

    auto load_tile = [&](int it, int buf) {
        float* As = sm + buf * STAGE_F;
        float* Bs = As + BM * ALD;
        int k0 = it << 5;
#pragma unroll
        for (int t = 0; t < 8; t++) {
            int g  = tid + t * 256;
            int m  = g >> 3;
            int kq = (g & 7) << 2;
            long long arow = (EPI == 2) ? (long long)(rowBase + m) : (long long)idx_sm[m];
            cp16(As + m * ALD + kq, A_ + arow * K + k0 + kq);
        }
#pragma unroll
        for (int t = 0; t < 4; t++) {
            int g  = tid + t * 256;
            int kk = g >> 5;
            int nq = (g & 31) << 2;
            cp16(Bs + kk * BLD + nq, B_ + (long long)(k0 + kk) * N + colBase + nq);
        }
        cp_commit();
    };

    load_tile(0, 0);
    for (int it = 0; it < nIt; it++) {
        if (it + 1 < nIt) { load_tile(it + 1, (it + 1) & 1); cp_wait1(); }
        else cp_wait0();
        __syncthreads();

        float* As = sm + (it & 1) * STAGE_F;
        float* Bs = As + BM * ALD;
#pragma unroll
        for (int ks = 0; ks < 4; ks++) {
            wmma::fragment<wmma::matrix_a, 16, 16, 8, wmma::precision::tf32, wmma::row_major> a[4];
            wmma::fragment<wmma::matrix_b, 16, 16, 8, wmma::precision::tf32, wmma::row_major> b[4];
#pragma unroll
            for (int i = 0; i < 4; i++)
                wmma::load_matrix_sync(a[i], As + (wr * 64 + i * 16) * ALD + ks * 8, ALD);
#pragma unroll
            for (int j = 0; j < 4; j++)
                wmma::load_matrix_sync(b[j], Bs + (ks * 8) * BLD + wc * 64 + j * 16, BLD);
#pragma unroll
            for (int i = 0; i < 4; i++)
#pragma unroll
                for (int j = 0; j < 4; j++)
                    wmma::mma_sync(acc[i][j], a[i], b[j], acc[i][j]);
        }
        __syncthreads();
    }

    if (EPI == 0 || EPI == 3) {
#pragma unroll
        for (int i = 0; i < 4; i++)
#pragma unroll
            for (int j = 0; j < 4; j++) {
                long long m = rowBase + wr * 64 + i * 16;
                long long n = colBase + wc * 64 + j * 16;
                wmma::store_matrix_sync(C_ + m * N + n, acc[i][j], N, wmma::mem_row_major);
            }
    } else {
        float* Csm = sm;   // 128 x 132 staging, two halves
#pragma unroll
        for (int half = 0; half < 2; half++) {
            if ((wr >> 1) == half) {
#pragma unroll
                for (int i = 0; i < 4; i++)
#pragma unroll
                    for (int j = 0; j < 4; j++)
                        wmma::store_matrix_sync(Csm + ((wr & 1) * 64 + i * 16) * BLD + wc * 64 + j * 16,
                                                acc[i][j], BLD, wmma::mem_row_major);
            }
            __syncthreads();
#pragma unroll
            for (int t = 0; t < 64; t++) {
                int idx = tid + t * 256;
                int m = idx >> 7, n = idx & 127;
                int gmRow = rowBase + half * 128 + m;
                if (EPI == 1) {
                    long long gm = (long long)gmRow * N + colBase + n;
                    float v = Csm[m * BLD + n] + resid[gm];
                    C_[gm] = v;
                    if (C1) C1[gm] = v;      // dual store (out buffer)
                } else { // EPI 2
                    atomicAdd(&C_[(long long)idx_sm[half * 128 + m] * N + colBase + n],
                              Csm[m * BLD + n] * scl_sm[half * 128 + m]);
                }
            }
            __syncthreads();
        }
    }
}

// ---------------------------------------------------------------------------
// RoPE
// ---------------------------------------------------------------------------
__global__ void rope_kernel(float* __restrict__ q, float* __restrict__ k)
{
    int idx = blockIdx.x * blockDim.x + threadIdx.x;
    if (idx >= T_TOK * NH * (HD / 2)) return;
    int j   = idx & 31;
    int hh  = (idx >> 5) & 15;
    int row = idx >> 9;
    int s   = row & (SEQ - 1);

    float inv = (float)(1.0 / pow(10000.0, (double)j / 32.0));
    float ang = (float)s * inv;
    float c = cosf(ang), sn = sinf(ang);

    long long base = (long long)row * DMODEL + hh * HD;
    float q1 = q[base + j], q2 = q[base + j + 32];
    q[base + j]      = q1 * c - q2 * sn;
    q[base + j + 32] = q2 * c + q1 * sn;
    float k1 = k[base + j], k2 = k[base + j + 32];
    k[base + j]      = k1 * c - k2 * sn;
    k[base + j + 32] = k2 * c + k1 * sn;
}

// ---------------------------------------------------------------------------
// FA2-style flash attention on raw mma.sync m16n8k8 tf32.
// Block: 128 q-rows, 8 warps (16 rows/warp), K/V tiles of 64 keys cp.async
// double-buffered. S/O accumulators register-resident. Q staged via smem.
// ---------------------------------------------------------------------------
#define KLD 68            // K tile ld: bank = 4g+t unique per warp quad-read
#define VLD 72            // V tile ld: bank = 8t+g unique
#define QLD 68            // Q staging ld (conflict-free readback)
#define KV_STAGE_F (64 * KLD + 64 * VLD)          // 8960 floats per stage
#define ATT_SMEM_BYTES (2 * KV_STAGE_F * 4)       // 71680 B (Q stage fits in stage0)

__global__ __launch_bounds__(256, 2)
void attn_kernel(const float* __restrict__ q,
                 const float* __restrict__ k,
                 const float* __restrict__ v,
                 float* __restrict__ o)
{
    extern __shared__ float sm[];

    int qt = blockIdx.x, h = blockIdx.y, b = blockIdx.z;
    int i0 = qt * 128;
    int tid  = threadIdx.x;
    int w    = tid >> 5;
    int lane = tid & 31;
    int g    = lane >> 2;      // groupID 0..7
    int t    = lane & 3;       // threadID in group 0..3
    long long base = ((long long)b * SEQ) * DMODEL + h * HD;

    int r0 = i0 + w * 16 + g;  // global seq row (first)
    int r1 = r0 + 8;           // second row

    // ---- stage Q through smem (coalesced), read A-fragments to registers ----
    unsigned qa[8][4];
    {
        float* Qs = sm;   // reuse stage-0 area before pipeline starts
#pragma unroll
        for (int u = 0; u < 2; u++) {
            int gidx = tid + u * 256;          // 0..511 -> 128 rows x 4 float4
            int row  = gidx >> 2;              // 0..127
            int c4   = (gidx & 3) << 4;        // 0,16,32,48
#pragma unroll
            for (int q4 = 0; q4 < 4; q4++) {
                float4 val = *(const float4*)(q + base + (long long)(i0 + row) * DMODEL + c4 + q4 * 4);
                val.x *= 0.125f; val.y *= 0.125f; val.z *= 0.125f; val.w *= 0.125f;
                *(float4*)(Qs + row * QLD + c4 + q4 * 4) = val;
            }
        }
        __syncthreads();
        int lr0 = w * 16 + g, lr1 = lr0 + 8;
#pragma unroll
        for (int kc = 0; kc < 8; kc++) {
            qa[kc][0] = __float_as_uint(Qs[lr0 * QLD + kc * 8 + t]);
            qa[kc][1] = __float_as_uint(Qs[lr1 * QLD + kc * 8 + t]);
            qa[kc][2] = __float_as_uint(Qs[lr0 * QLD + kc * 8 + t + 4]);
            qa[kc][3] = __float_as_uint(Qs[lr1 * QLD + kc * 8 + t + 4]);
        }
        __syncthreads();
    }

    float m0 = -1e30f, m1 = -1e30f, l0 = 0.f, l1 = 0.f;
    float oacc[8][4];
#pragma unroll
    for (int nb = 0; nb < 8; nb++)
#pragma unroll
        for (int u = 0; u < 4; u++) oacc[nb][u] = 0.f;

    int jstart = i0 - (WINDOW - 1); if (jstart < 0) jstart = 0;
    int jt0 = jstart >> 6;
    int jt1 = (i0 + 127) >> 6;
    int nTiles = jt1 - jt0 + 1;

    auto loadKV = [&](int jt, int stage) {
        float* Ks = sm + stage * KV_STAGE_F;
        float* Vs = Ks + 64 * KLD;
        int j0 = jt << 6;
#pragma unroll
        for (int u = 0; u < 4; u++) {
            int gidx = tid + u * 256;          // 0..1023
            int row  = gidx >> 4;              // 0..63
            int c4   = (gidx & 15) << 2;       // 0..60
            long long gp = base + (long long)(j0 + row) * DMODEL + c4;
            cp16(Ks + row * KLD + c4, k + gp);
            cp16(Vs + row * VLD + c4, v + gp);
        }
        cp_commit();
    };

    loadKV(jt0, 0);
    for (int it = 0; it < nTiles; it++) {
        int j0 = (jt0 + it) << 6;
        if (it + 1 < nTiles) { loadKV(jt0 + it + 1, (it + 1) & 1); cp_wait1(); }
        else cp_wait0();
        __syncthreads();

        float* Ks = sm + (it & 1) * KV_STAGE_F;
        float* Vs = Ks + 64 * KLD;

        // ---- S = Q @ K^T (registers) ----
        float sc[8][4];
#pragma unroll
        for (int kb = 0; kb < 8; kb++) {
            float d0 = 0.f, d1 = 0.f, d2 = 0.f, d3 = 0.f;
            const float* krow = Ks + (kb * 8 + g) * KLD;
#pragma unroll
            for (int kc = 0; kc < 8; kc++) {
                unsigned b0 = __float_as_uint(krow[kc * 8 + t]);
                unsigned b1 = __float_as_uint(krow[kc * 8 + t + 4]);
                mma_tf32(d0, d1, d2, d3, qa[kc][0], qa[kc][1], qa[kc][2], qa[kc][3], b0, b1);
            }
            sc[kb][0] = d0; sc[kb][1] = d1; sc[kb][2] = d2; sc[kb][3] = d3;
        }

        // ---- masked online softmax (registers) ----
        float tm0 = -1e30f, tm1 = -1e30f;
#pragma unroll
        for (int kb = 0; kb < 8; kb++) {
            int c0 = j0 + kb * 8 + 2 * t;
            int c1 = c0 + 1;
            int d00 = r0 - c0, d01 = r0 - c1, d10 = r1 - c0, d11 = r1 - c1;
            if (d00 >= 0 && d00 < WINDOW) tm0 = fmaxf(tm0, sc[kb][0]);
            if (d01 >= 0 && d01 < WINDOW) tm0 = fmaxf(tm0, sc[kb][1]);
            if (d10 >= 0 && d10 < WINDOW) tm1 = fmaxf(tm1, sc[kb][2]);
            if (d11 >= 0 && d11 < WINDOW) tm1 = fmaxf(tm1, sc[kb][3]);
        }
        tm0 = fmaxf(tm0, __shfl_xor_sync(0xffffffffu, tm0, 1));
        tm0 = fmaxf(tm0, __shfl_xor_sync(0xffffffffu, tm0, 2));
        tm1 = fmaxf(tm1, __shfl_xor_sync(0xffffffffu, tm1, 1));
        tm1 = fmaxf(tm1, __shfl_xor_sync(0xffffffffu, tm1, 2));

        float mn0 = fmaxf(m0, tm0);
        float mn1 = fmaxf(m1, tm1);
        float alpha0 = __expf(m0 - mn0);
        float alpha1 = __expf(m1 - mn1);
        m0 = mn0; m1 = mn1;

        float sum0 = 0.f, sum1 = 0.f;
#pragma unroll
        for (int kb = 0; kb < 8; kb++) {
            int c0 = j0 + kb * 8 + 2 * t;
            int c1 = c0 + 1;
            int d00 = r0 - c0, d01 = r0 - c1, d10 = r1 - c0, d11 = r1 - c1;
            float p00 = (d00 >= 0 && d00 < WINDOW) ? __expf(sc[kb][0] - mn0) : 0.f;
            float p01 = (d01 >= 0 && d01 < WINDOW) ? __expf(sc[kb][1] - mn0) : 0.f;
            float p10 = (d10 >= 0 && d10 < WINDOW) ? __expf(sc[kb][2] - mn1) : 0.f;
            float p11 = (d11 >= 0 && d11 < WINDOW) ? __expf(sc[kb][3] - mn1) : 0.f;
            sc[kb][0] = p00; sc[kb][1] = p01; sc[kb][2] = p10; sc[kb][3] = p11;
            sum0 += p00 + p01;
            sum1 += p10 + p11;
        }
        sum0 += __shfl_xor_sync(0xffffffffu, sum0, 1);
        sum0 += __shfl_xor_sync(0xffffffffu, sum0, 2);
        sum1 += __shfl_xor_sync(0xffffffffu, sum1, 1);
        sum1 += __shfl_xor_sync(0xffffffffu, sum1, 2);
        l0 = l0 * alpha0 + sum0;
        l1 = l1 * alpha1 + sum1;

        // scale O accumulators
#pragma unroll
        for (int nb = 0; nb < 8; nb++) {
            oacc[nb][0] *= alpha0; oacc[nb][1] *= alpha0;
            oacc[nb][2] *= alpha1; oacc[nb][3] *= alpha1;
        }

        // ---- O += P @ V ----
        int srcA = (lane & ~3) | (t >> 1);
        int srcB = srcA + 2;
#pragma unroll
        for (int kb = 0; kb < 8; kb++) {
            // convert P (C layout, cols 2t/2t+1) -> A operand (cols t, t+4)
            float v0, v1;
            v0 = __shfl_sync(0xffffffffu, sc[kb][0], srcA);
            v1 = __shfl_sync(0xffffffffu, sc[kb][1], srcA);
            unsigned pa0 = __float_as_uint((t & 1) ? v1 : v0);
            v0 = __shfl_sync(0xffffffffu, sc[kb][2], srcA);
            v1 = __shfl_sync(0xffffffffu, sc[kb][3], srcA);
            unsigned pa1 = __float_as_uint((t & 1) ? v1 : v0);
            v0 = __shfl_sync(0xffffffffu, sc[kb][0], srcB);
            v1 = __shfl_sync(0xffffffffu, sc[kb][1], srcB);
            unsigned pa2 = __float_as_uint((t & 1) ? v1 : v0);
            v0 = __shfl_sync(0xffffffffu, sc[kb][2], srcB);
            v1 = __shfl_sync(0xffffffffu, sc[kb][3], srcB);
            unsigned pa3 = __float_as_uint((t & 1) ? v1 : v0);

            const float* vrow0 = Vs + (kb * 8 + t) * VLD;
            const float* vrow1 = Vs + (kb * 8 + t + 4) * VLD;
#pragma unroll
            for (int nb = 0; nb < 8; nb++) {
                unsigned b0 = __float_as_uint(vrow0[nb * 8 + g]);
                unsigned b1 = __float_as_uint(vrow1[nb * 8 + g]);
                mma_tf32(oacc[nb][0], oacc[nb][1], oacc[nb][2], oacc[nb][3],
                         pa0, pa1, pa2, pa3, b0, b1);
            }
        }
        __syncthreads();
    }

    // ---- write normalized output ----
    float rl0 = 1.f / l0;
    float rl1 = 1.f / l1;
#pragma unroll
    for (int nb = 0; nb < 8; nb++) {
        float2 o0 = make_float2(oacc[nb][0] * rl0, oacc[nb][1] * rl0);
        float2 o1 = make_float2(oacc[nb][2] * rl1, oacc[nb][3] * rl1);
        *(float2*)(o + base + (long long)r0 * DMODEL + nb * 8 + 2 * t) = o0;
        *(float2*)(o + base + (long long)r1 * DMODEL + nb * 8 + 2 * t) = o1;
    }
}

// ---------------------------------------------------------------------------
// Gating
// ---------------------------------------------------------------------------
__global__ void gate_kernel(const float* __restrict__ xn2,
                            const float* __restrict__ gw,
                            float* __restrict__ wte,
                            float* __restrict__ phis)
{
    int tok  = (blockIdx.x * blockDim.x + threadIdx.x) >> 5;
    int lane = threadIdx.x & 31;
    if (tok >= T_TOK) return;
    const float* xr = xn2 + (long long)tok * DMODEL;
    float acc[NE];
#pragma unroll
    for (int e = 0; e < NE; e++) acc[e] = 0.f;
    for (int d = lane; d < DMODEL; d += 32) {
        float xv = xr[d];
        const float* g = gw + d * NE;
#pragma unroll
        for (int e = 0; e < NE; e++) acc[e] = fmaf(xv, g[e], acc[e]);
    }
#pragma unroll
    for (int e = 0; e < NE; e++)
#pragma unroll
        for (int off = 16; off; off >>= 1)
            acc[e] += __shfl_xor_sync(0xffffffffu, acc[e], off);

    if (lane == 0) {
        float mx = acc[0];
#pragma unroll
        for (int e = 1; e < NE; e++) mx = fmaxf(mx, acc[e]);
        float p[NE], s = 0.f;
#pragma unroll
        for (int e = 0; e < NE; e++) { p[e] = expf(acc[e] - mx); s += p[e]; }
#pragma unroll
        for (int e = 0; e < NE; e++) p[e] /= s;
        int i1 = 0;
#pragma unroll
        for (int e = 1; e < NE; e++) if (p[e] > p[i1]) i1 = e;
        int i2 = -1;
#pragma unroll
        for (int e = 0; e < NE; e++)
            if (e != i1 && (i2 < 0 || p[e] > p[i2])) i2 = e;
#pragma unroll
        for (int e = 0; e < NE; e++)
            wte[(long long)tok * NE + e] = (e == i1) ? p[i1] : (e == i2) ? p[i2] : 0.f;
#pragma unroll
        for (int e = 0; e < NE; e++) atomicAdd(&phis[e], p[e]);
    }
}

// ---------------------------------------------------------------------------
// Per-expert top-CAP selection (bitonic, stable)
// ---------------------------------------------------------------------------
__global__ void expert_topk_kernel(const float* __restrict__ wte,
                                   int* __restrict__ capidx,
                                   float* __restrict__ capval)
{
    __shared__ float sv[T_TOK];
    __shared__ int   si[T_TOK];
    int e = blockIdx.x;
    for (int i = threadIdx.x; i < T_TOK; i += 1024) {
        sv[i] = wte[(long long)i * NE + e];
        si[i] = i;
    }
    __syncthreads();
    for (int kk = 2; kk <= T_TOK; kk <<= 1) {
        for (int j = kk >> 1; j > 0; j >>= 1) {
            for (int i = threadIdx.x; i < T_TOK; i += 1024) {
                int l = i ^ j;
                if (l > i) {
                    bool dir = ((i & kk) == 0);
                    float vi = sv[i], vl = sv[l];
                    int   xi = si[i], xl = si[l];
                    bool before = (vi > vl) || (vi == vl && xi < xl);
                    if (before != dir) {
                        sv[i] = vl; sv[l] = vi;
                        si[i] = xl; si[l] = xi;
                    }
                }
            }
            __syncthreads();
        }
    }
    for (int i = threadIdx.x; i < CAP; i += 1024) {
        capidx[e * CAP + i] = si[i];
        capval[e * CAP + i] = sv[i];
    }
}

// ---------------------------------------------------------------------------
// SwiGLU (vectorized)
// ---------------------------------------------------------------------------
__global__ void act_kernel(const float* __restrict__ hid, float* __restrict__ act)
{
    long long idx4 = (long long)blockIdx.x * blockDim.x + threadIdx.x;
    if (idx4 >= (long long)NE * CAP * DFF / 4) return;
    int f4 = (int)(idx4 % (DFF / 4));
    long long row = idx4 / (DFF / 4);
    const float4 h1 = *(const float4*)(hid + row * (2 * DFF) + f4 * 4);
    const float4 h2 = *(const float4*)(hid + row * (2 * DFF) + DFF + f4 * 4);
    float4 r;
    r.x = h1.x * (h2.x / (1.f + __expf(-h2.x)));
    r.y = h1.y * (h2.y / (1.f + __expf(-h2.y)));
    r.z = h1.z * (h2.z / (1.f + __expf(-h2.z)));
    r.w = h1.w * (h2.w / (1.f + __expf(-h2.w)));
    *(float4*)(act + row * DFF + f4 * 4) = r;
}

// ---------------------------------------------------------------------------
// Utility
// ---------------------------------------------------------------------------
__global__ void zero_phis_kernel(float* __restrict__ phis)
{
    if (threadIdx.x < NE) phis[threadIdx.x] = 0.f;
}

__global__ void aux_kernel(const float* __restrict__ phis, float* __restrict__ out, int out_size)
{
    if (out_size > OUT_MAIN) {
        float s = 0.f;
#pragma unroll
        for (int e = 0; e < NE; e++) {
            float pm = phis[e] / (float)T_TOK;
            s += pm * pm;
        }
        out[OUT_MAIN] = (float)NE * s;
    }
}

// ---------------------------------------------------------------------------
// Launch
// ---------------------------------------------------------------------------
extern "C" void kernel_launch(void* const* d_in, const int* in_sizes, int n_in,
                              void* d_out, int out_size)
{
    const float* x   = (const float*)d_in[0];
    const float* wq  = (const float*)d_in[1];
    const float* wk  = (const float*)d_in[2];
    const float* wv  = (const float*)d_in[3];
    const float* wo  = (const float*)d_in[4];
    const float* n1w = (const float*)d_in[5];
    const float* n2w = (const float*)d_in[6];
    const float* gw  = (const float*)d_in[7];
    const float* w1  = (const float*)d_in[8];
    const float* w2  = (const float*)d_in[9];
    float* out = (float*)d_out;

    float *xn, *qb, *kb, *vb, *ao, *hb, *xn2, *wte, *hid, *act, *capv, *phis;
    int* capi;
    cudaGetSymbolAddress((void**)&xn,  g_xn);
    cudaGetSymbolAddress((void**)&qb,  g_q);
    cudaGetSymbolAddress((void**)&kb,  g_k);
    cudaGetSymbolAddress((void**)&vb,  g_v);
    cudaGetSymbolAddress((void**)&ao,  g_ao);
    cudaGetSymbolAddress((void**)&hb,  g_h);
    cudaGetSymbolAddress((void**)&xn2, g_xn2);
    cudaGetSymbolAddress((void**)&wte, g_wte);
    cudaGetSymbolAddress((void**)&hid, g_hid);
    cudaGetSymbolAddress((void**)&act, g_act);
    cudaGetSymbolAddress((void**)&capi, g_capidx);
    cudaGetSymbolAddress((void**)&capv, g_capval);
    cudaGetSymbolAddress((void**)&phis, g_phis);

    static int attr_done = 0;
    if (!attr_done) {
        cudaFuncSetAttribute(wgemm_kernel<0>, cudaFuncAttributeMaxDynamicSharedMemorySize, GEMM_SMEM_BYTES);
        cudaFuncSetAttribute(wgemm_kernel<1>, cudaFuncAttributeMaxDynamicSharedMemorySize, GEMM_SMEM_BYTES);
        cudaFuncSetAttribute(wgemm_kernel<2>, cudaFuncAttributeMaxDynamicSharedMemorySize, GEMM_SMEM_BYTES);
        cudaFuncSetAttribute(wgemm_kernel<3>, cudaFuncAttributeMaxDynamicSharedMemorySize, GEMM_SMEM_BYTES);
        cudaFuncSetAttribute(attn_kernel, cudaFuncAttributeMaxDynamicSharedMemorySize, ATT_SMEM_BYTES);
        attr_done = 1;
    }

    // ---- sublayer 1 ----
    rmsnorm_kernel<<<T_TOK, 256>>>(x, n1w, xn);

    // Fused QKV: grid.x = 3 weights x 8 col-blocks, grid.y = 4096/256
    wgemm_kernel<3><<<dim3(24, T_TOK / BM, 1), 256, GEMM_SMEM_BYTES>>>(
        xn, wq, wk, wv, qb, kb, vb, nullptr, nullptr, nullptr, nullptr,
        DMODEL, DMODEL, 0, 0, 0, 0);

    rope_kernel<<<(T_TOK * NH * 32 + 255) / 256, 256>>>(qb, kb);

    attn_kernel<<<dim3(SEQ / 128, NH, NB), 256, ATT_SMEM_BYTES>>>(qb, kb, vb, ao);

    // O-proj + residual, dual-stored to h and out (removes copy kernel)
    wgemm_kernel<1><<<dim3(DMODEL / BN, T_TOK / BM, 1), 256, GEMM_SMEM_BYTES>>>(
        ao, wo, nullptr, nullptr, hb, out, nullptr, x, nullptr, nullptr, nullptr,
        DMODEL, DMODEL, 0, 0, 0, 0);

    // ---- sublayer 2: MoE ----
    rmsnorm_kernel<<<T_TOK, 256>>>(hb, n2w, xn2);

    zero_phis_kernel<<<1, 32>>>(phis);
    gate_kernel<<<(T_TOK * 32) / 256, 256>>>(xn2, gw, wte, phis);
    expert_topk_kernel<<<NE, 1024>>>(wte, capi, capv);

    // hidden[e] = xn2[capidx[e]] @ w1[e]   (M=512, N=4096, K=1024)
    wgemm_kernel<0><<<dim3((2 * DFF) / BN, CAP / BM, NE), 256, GEMM_SMEM_BYTES>>>(
        xn2, w1, nullptr, nullptr, hid, nullptr, nullptr, nullptr, capi, nullptr, nullptr,
        2 * DFF, DMODEL,
        0, (long long)DMODEL * 2 * DFF, (long long)CAP * 2 * DFF, CAP);

    act_kernel<<<(NE * CAP * DFF / 4 + 255) / 256, 256>>>(hid, act);

    // out[capidx[e][c]] += (act[e] @ w2[e])[c] * capval[e][c]  (M=512,N=1024,K=2048)
    wgemm_kernel<2><<<dim3(DMODEL / BN, CAP / BM, NE), 256, GEMM_SMEM_BYTES>>>(
        act, w2, nullptr, nullptr, out, nullptr, nullptr, nullptr, nullptr, capi, capv,
        DMODEL, DFF,
        (long long)CAP * DFF, (long long)DFF * DMODEL, 0, CAP);

    aux_kernel<<<1, 1>>>(phis, out, out_size);

    (void)in_sizes; (void)n_in;
}

// round 13
// speedup vs baseline: 2.1833x; 1.2200x over previous
#include <cuda_runtime.h>
#include <cstdint>
#include <math.h>
#include <mma.h>

using namespace nvcuda;

// ---------------------------------------------------------------------------
// Problem constants
// ---------------------------------------------------------------------------
#define NB     2
#define SEQ    2048
#define T_TOK  4096
#define DMODEL 1024
#define NH     16
#define HD     64
#define WINDOW 1024
#define NE     8
#define DFF    2048
#define CAP    512
#define OUT_MAIN (T_TOK * DMODEL)

// ---------------------------------------------------------------------------
// Scratch
// ---------------------------------------------------------------------------
__device__ float g_xn  [T_TOK * DMODEL];
__device__ float g_q   [T_TOK * DMODEL];
__device__ float g_k   [T_TOK * DMODEL];
__device__ float g_v   [T_TOK * DMODEL];
__device__ float g_ao  [T_TOK * DMODEL];
__device__ float g_h   [T_TOK * DMODEL];
__device__ float g_xn2 [T_TOK * DMODEL];
__device__ float g_wte [T_TOK * NE];
__device__ float g_hid [NE * CAP * 2 * DFF];
__device__ float g_act [NE * CAP * DFF];
__device__ int   g_capidx[NE * CAP];
__device__ float g_capval[NE * CAP];
__device__ float g_phis[NE];

// ---------------------------------------------------------------------------
// cp.async helpers
// ---------------------------------------------------------------------------
__device__ __forceinline__ void cp16(void* dst, const void* src)
{
    unsigned int d = (unsigned int)__cvta_generic_to_shared(dst);
    asm volatile("cp.async.cg.shared.global [%0], [%1], 16;\n" :: "r"(d), "l"(src));
}
__device__ __forceinline__ void cp_commit() { asm volatile("cp.async.commit_group;\n"); }
__device__ __forceinline__ void cp_wait2()  { asm volatile("cp.async.wait_group 2;\n"); }
__device__ __forceinline__ void cp_wait1()  { asm volatile("cp.async.wait_group 1;\n"); }
__device__ __forceinline__ void cp_wait0()  { asm volatile("cp.async.wait_group 0;\n"); }

// mma.sync m16n8k8 tf32: D = A*B + D.  Operands as raw b32 (truncated tf32).
__device__ __forceinline__ void mma_tf32(float& d0, float& d1, float& d2, float& d3,
                                         unsigned a0, unsigned a1, unsigned a2, unsigned a3,
                                         unsigned b0, unsigned b1)
{
    asm volatile(
        "mma.sync.aligned.m16n8k8.row.col.f32.tf32.tf32.f32 "
        "{%0,%1,%2,%3},{%4,%5,%6,%7},{%8,%9},{%0,%1,%2,%3};\n"
        : "+f"(d0), "+f"(d1), "+f"(d2), "+f"(d3)
        : "r"(a0), "r"(a1), "r"(a2), "r"(a3), "r"(b0), "r"(b1));
}

// ---------------------------------------------------------------------------
// RMSNorm
// ---------------------------------------------------------------------------
__global__ void rmsnorm_kernel(const float* __restrict__ x,
                               const float* __restrict__ w,
                               float* __restrict__ o)
{
    int row = blockIdx.x;
    const float* xr = x + (long long)row * DMODEL;
    float vals[4];
    float ss = 0.f;
#pragma unroll
    for (int t = 0; t < 4; t++) {
        float v = xr[threadIdx.x + t * 256];
        vals[t] = v;
        ss += v * v;
    }
    __shared__ float red[8];
#pragma unroll
    for (int off = 16; off; off >>= 1)
        ss += __shfl_xor_sync(0xffffffffu, ss, off);
    if ((threadIdx.x & 31) == 0) red[threadIdx.x >> 5] = ss;
    __syncthreads();
    if (threadIdx.x == 0) {
        float s = 0.f;
#pragma unroll
        for (int i = 0; i < 8; i++) s += red[i];
        red[0] = s;
    }
    __syncthreads();
    float rinv = 1.f / sqrtf(red[0] / (float)DMODEL + 1e-6f);
    float* orow = o + (long long)row * DMODEL;
#pragma unroll
    for (int t = 0; t < 4; t++) {
        int d = threadIdx.x + t * 256;
        orow[d] = vals[t] * rinv * w[d];
    }
}

// ---------------------------------------------------------------------------
// WMMA tf32 GEMM (truncated tf32), 3-stage cp.async pipeline.
// CTA tile 256x128, BK=32, 256 threads, 8 warps each 64x64 (4x2 warp grid).
// EPI 0: plain. EPI 1: += resid, dual-store (C0 and C1 if non-null).
// EPI 2: scatter atomicAdd * rowScale. EPI 3: fused QKV.
// ---------------------------------------------------------------------------
#define BM 256
#define BN 128
#define ALD 36
#define BLD 132
#define STAGE_F (BM * ALD + 32 * BLD)      // 13440 floats
#define GEMM_SMEM_BYTES (3 * STAGE_F * 4)  // 161280 B

template<int EPI>
__global__ __launch_bounds__(256)
void wgemm_kernel(const float* __restrict__ A,
                  const float* __restrict__ B0,
                  const float* __restrict__ B1,
                  const float* __restrict__ B2,
                  float* __restrict__ C0,
                  float* __restrict__ C1,
                  float* __restrict__ C2,
                  const float* __restrict__ resid,
                  const int*  __restrict__ rowIdxA,
                  const int*  __restrict__ outIdx,
                  const float* __restrict__ rowScale,
                  int N, int K,
                  long long aB, long long bB, long long cB, int idxB)
{
    extern __shared__ float sm[];
    __shared__ int   idx_sm[BM];
    __shared__ float scl_sm[BM];

    int e = blockIdx.z;
    const float* A_ = A + (long long)e * aB;
    const float* B_;
    float* C_;
    int colBase;
    if (EPI == 3) {
        int sel = blockIdx.x >> 3;
        colBase = (blockIdx.x & 7) * BN;
        B_ = (sel == 0) ? B0 : (sel == 1) ? B1 : B2;
        C_ = (sel == 0) ? C0 : (sel == 1) ? C1 : C2;
    } else {
        colBase = blockIdx.x * BN;
        B_ = B0 + (long long)e * bB;
        C_ = C0 + (long long)e * cB;
    }

    int tid = threadIdx.x;
    int w   = tid >> 5;
    int wr  = w >> 1;         // 0..3  (64-row band)
    int wc  = w & 1;          // 0..1  (64-col band)
    int rowBase = blockIdx.y * BM;

    {
        int ar = rowBase + tid;
        idx_sm[tid] = (EPI == 0 && rowIdxA) ? rowIdxA[e * idxB + ar] : ar;
        if (EPI == 2) {
            scl_sm[tid] = rowScale[e * idxB + ar];
            idx_sm[tid] = outIdx[e * idxB + ar];   // scatter target rows
        }
    }
    __syncthreads();

    wmma::fragment<wmma::accumulator, 16, 16, 8, float> acc[4][4];
#pragma unroll
    for (int i = 0; i < 4; i++)
#pragma unroll
        for (int j = 0; j < 4; j++) wmma::fill_fragment(acc[i][j], 0.f);

    int nIt = K >> 5;

    auto load_tile = [&](int it, int buf) {
        float* As = sm + buf * STAGE_F;
        float* Bs = As + BM * ALD;
        int k0 = it << 5;
#pragma unroll
        for (int t = 0; t < 8; t++) {
            int g  = tid + t * 256;
            int m  = g >> 3;
            int kq = (g & 7) << 2;
            long long arow = (EPI == 2) ? (long long)(rowBase + m) : (long long)idx_sm[m];
            cp16(As + m * ALD + kq, A_ + arow * K + k0 + kq);
        }
#pragma unroll
        for (int t = 0; t < 4; t++) {
            int g  = tid + t * 256;
            int kk = g >> 5;
            int nq = (g & 31) << 2;
            cp16(Bs + kk * BLD + nq, B_ + (long long)(k0 + kk) * N + colBase + nq);
        }
        cp_commit();
    };

    load_tile(0, 0);
    if (nIt > 1) load_tile(1, 1);
    int stage = 0;
    for (int it = 0; it < nIt; it++) {
        if (it + 2 < nIt) {
            load_tile(it + 2, (stage + 2) % 3);
            cp_wait2();
        } else if (it + 1 < nIt) {
            cp_wait1();
        } else {
            cp_wait0();
        }
        __syncthreads();

        float* As = sm + stage * STAGE_F;
        float* Bs = As + BM * ALD;
#pragma unroll
        for (int ks = 0; ks < 4; ks++) {
            wmma::fragment<wmma::matrix_a, 16, 16, 8, wmma::precision::tf32, wmma::row_major> a[4];
            wmma::fragment<wmma::matrix_b, 16, 16, 8, wmma::precision::tf32, wmma::row_major> b[4];
#pragma unroll
            for (int i = 0; i < 4; i++)
                wmma::load_matrix_sync(a[i], As + (wr * 64 + i * 16) * ALD + ks * 8, ALD);
#pragma unroll
            for (int j = 0; j < 4; j++)
                wmma::load_matrix_sync(b[j], Bs + (ks * 8) * BLD + wc * 64 + j * 16, BLD);
#pragma unroll
            for (int i = 0; i < 4; i++)
#pragma unroll
                for (int j = 0; j < 4; j++)
                    wmma::mma_sync(acc[i][j], a[i], b[j], acc[i][j]);
        }
        __syncthreads();
        stage = (stage + 1) % 3;
    }

    if (EPI == 0 || EPI == 3) {
#pragma unroll
        for (int i = 0; i < 4; i++)
#pragma unroll
            for (int j = 0; j < 4; j++) {
                long long m = rowBase + wr * 64 + i * 16;
                long long n = colBase + wc * 64 + j * 16;
                wmma::store_matrix_sync(C_ + m * N + n, acc[i][j], N, wmma::mem_row_major);
            }
    } else {
        float* Csm = sm;   // 128 x 132 staging, two halves
#pragma unroll
        for (int half = 0; half < 2; half++) {
            if ((wr >> 1) == half) {
#pragma unroll
                for (int i = 0; i < 4; i++)
#pragma unroll
                    for (int j = 0; j < 4; j++)
                        wmma::store_matrix_sync(Csm + ((wr & 1) * 64 + i * 16) * BLD + wc * 64 + j * 16,
                                                acc[i][j], BLD, wmma::mem_row_major);
            }
            __syncthreads();
#pragma unroll
            for (int t = 0; t < 64; t++) {
                int idx = tid + t * 256;
                int m = idx >> 7, n = idx & 127;
                int gmRow = rowBase + half * 128 + m;
                if (EPI == 1) {
                    long long gm = (long long)gmRow * N + colBase + n;
                    float v = Csm[m * BLD + n] + resid[gm];
                    C_[gm] = v;
                    if (C1) C1[gm] = v;      // dual store (out buffer)
                } else { // EPI 2
                    atomicAdd(&C_[(long long)idx_sm[half * 128 + m] * N + colBase + n],
                              Csm[m * BLD + n] * scl_sm[half * 128 + m]);
                }
            }
            __syncthreads();
        }
    }
}

// ---------------------------------------------------------------------------
// RoPE (f32 exp2 for inv_freq; reference computes inv_freq in f32 too)
// ---------------------------------------------------------------------------
__global__ void rope_kernel(float* __restrict__ q, float* __restrict__ k)
{
    int idx = blockIdx.x * blockDim.x + threadIdx.x;
    if (idx >= T_TOK * NH * (HD / 2)) return;
    int j   = idx & 31;
    int hh  = (idx >> 5) & 15;
    int row = idx >> 9;
    int s   = row & (SEQ - 1);

    // inv = 10000^(-j/32) = 2^(-j * log2(10000)/32)
    float inv = exp2f(-(float)j * 0.4152410118609203f);
    float ang = (float)s * inv;
    float c = cosf(ang), sn = sinf(ang);

    long long base = (long long)row * DMODEL + hh * HD;
    float q1 = q[base + j], q2 = q[base + j + 32];
    q[base + j]      = q1 * c - q2 * sn;
    q[base + j + 32] = q2 * c + q1 * sn;
    float k1 = k[base + j], k2 = k[base + j + 32];
    k[base + j]      = k1 * c - k2 * sn;
    k[base + j + 32] = k2 * c + k1 * sn;
}

// ---------------------------------------------------------------------------
// FA2-style flash attention on raw mma.sync m16n8k8 tf32.
// Block: 128 q-rows, 8 warps (16 rows/warp), K/V tiles of 64 keys cp.async
// double-buffered. S/O accumulators register-resident. Q staged via smem.
// Fully-in-window tiles take a mask-free fast path.
// ---------------------------------------------------------------------------
#define KLD 68            // K tile ld: bank = 4g+t unique per warp quad-read
#define VLD 72            // V tile ld: bank = 8t+g unique
#define QLD 68            // Q staging ld (conflict-free readback)
#define KV_STAGE_F (64 * KLD + 64 * VLD)          // 8960 floats per stage
#define ATT_SMEM_BYTES (2 * KV_STAGE_F * 4)       // 71680 B (Q stage fits in stage0)

__global__ __launch_bounds__(256, 2)
void attn_kernel(const float* __restrict__ q,
                 const float* __restrict__ k,
                 const float* __restrict__ v,
                 float* __restrict__ o)
{
    extern __shared__ float sm[];

    int qt = blockIdx.x, h = blockIdx.y, b = blockIdx.z;
    int i0 = qt * 128;
    int tid  = threadIdx.x;
    int w    = tid >> 5;
    int lane = tid & 31;
    int g    = lane >> 2;      // groupID 0..7
    int t    = lane & 3;       // threadID in group 0..3
    long long base = ((long long)b * SEQ) * DMODEL + h * HD;

    int r0base = i0 + w * 16;  // warp's first row
    int r0 = r0base + g;       // global seq row (first)
    int r1 = r0 + 8;           // second row

    // ---- stage Q through smem (coalesced), read A-fragments to registers ----
    unsigned qa[8][4];
    {
        float* Qs = sm;   // reuse stage-0 area before pipeline starts
#pragma unroll
        for (int u = 0; u < 2; u++) {
            int gidx = tid + u * 256;          // 0..511 -> 128 rows x 4 float4
            int row  = gidx >> 2;              // 0..127
            int c4   = (gidx & 3) << 4;        // 0,16,32,48
#pragma unroll
            for (int q4 = 0; q4 < 4; q4++) {
                float4 val = *(const float4*)(q + base + (long long)(i0 + row) * DMODEL + c4 + q4 * 4);
                val.x *= 0.125f; val.y *= 0.125f; val.z *= 0.125f; val.w *= 0.125f;
                *(float4*)(Qs + row * QLD + c4 + q4 * 4) = val;
            }
        }
        __syncthreads();
        int lr0 = w * 16 + g, lr1 = lr0 + 8;
#pragma unroll
        for (int kc = 0; kc < 8; kc++) {
            qa[kc][0] = __float_as_uint(Qs[lr0 * QLD + kc * 8 + t]);
            qa[kc][1] = __float_as_uint(Qs[lr1 * QLD + kc * 8 + t]);
            qa[kc][2] = __float_as_uint(Qs[lr0 * QLD + kc * 8 + t + 4]);
            qa[kc][3] = __float_as_uint(Qs[lr1 * QLD + kc * 8 + t + 4]);
        }
        __syncthreads();
    }

    float m0 = -1e30f, m1 = -1e30f, l0 = 0.f, l1 = 0.f;
    float oacc[8][4];
#pragma unroll
    for (int nb = 0; nb < 8; nb++)
#pragma unroll
        for (int u = 0; u < 4; u++) oacc[nb][u] = 0.f;

    int jstart = i0 - (WINDOW - 1); if (jstart < 0) jstart = 0;
    int jt0 = jstart >> 6;
    int jt1 = (i0 + 127) >> 6;
    int nTiles = jt1 - jt0 + 1;

    auto loadKV = [&](int jt, int stage) {
        float* Ks = sm + stage * KV_STAGE_F;
        float* Vs = Ks + 64 * KLD;
        int j0 = jt << 6;
#pragma unroll
        for (int u = 0; u < 4; u++) {
            int gidx = tid + u * 256;          // 0..1023
            int row  = gidx >> 4;              // 0..63
            int c4   = (gidx & 15) << 2;       // 0..60
            long long gp = base + (long long)(j0 + row) * DMODEL + c4;
            cp16(Ks + row * KLD + c4, k + gp);
            cp16(Vs + row * VLD + c4, v + gp);
        }
        cp_commit();
    };

    loadKV(jt0, 0);
    for (int it = 0; it < nTiles; it++) {
        int j0 = (jt0 + it) << 6;
        if (it + 1 < nTiles) { loadKV(jt0 + it + 1, (it + 1) & 1); cp_wait1(); }
        else cp_wait0();
        __syncthreads();

        float* Ks = sm + (it & 1) * KV_STAGE_F;
        float* Vs = Ks + 64 * KLD;

        // ---- S = Q @ K^T (registers) ----
        float sc[8][4];
#pragma unroll
        for (int kb = 0; kb < 8; kb++) {
            float d0 = 0.f, d1 = 0.f, d2 = 0.f, d3 = 0.f;
            const float* krow = Ks + (kb * 8 + g) * KLD;
#pragma unroll
            for (int kc = 0; kc < 8; kc++) {
                unsigned b0 = __float_as_uint(krow[kc * 8 + t]);
                unsigned b1 = __float_as_uint(krow[kc * 8 + t + 4]);
                mma_tf32(d0, d1, d2, d3, qa[kc][0], qa[kc][1], qa[kc][2], qa[kc][3], b0, b1);
            }
            sc[kb][0] = d0; sc[kb][1] = d1; sc[kb][2] = d2; sc[kb][3] = d3;
        }

        // ---- masked online softmax (registers) ----
        // Tile fully inside window for all 16 rows of this warp?
        bool full = (j0 + 63 <= r0base) && (j0 >= r0base + 16 - WINDOW);

        float tm0 = -1e30f, tm1 = -1e30f;
        if (full) {
#pragma unroll
            for (int kb = 0; kb < 8; kb++) {
                tm0 = fmaxf(tm0, fmaxf(sc[kb][0], sc[kb][1]));
                tm1 = fmaxf(tm1, fmaxf(sc[kb][2], sc[kb][3]));
            }
        } else {
#pragma unroll
            for (int kb = 0; kb < 8; kb++) {
                int c0 = j0 + kb * 8 + 2 * t;
                int c1 = c0 + 1;
                int d00 = r0 - c0, d01 = r0 - c1, d10 = r1 - c0, d11 = r1 - c1;
                if (d00 >= 0 && d00 < WINDOW) tm0 = fmaxf(tm0, sc[kb][0]);
                if (d01 >= 0 && d01 < WINDOW) tm0 = fmaxf(tm0, sc[kb][1]);
                if (d10 >= 0 && d10 < WINDOW) tm1 = fmaxf(tm1, sc[kb][2]);
                if (d11 >= 0 && d11 < WINDOW) tm1 = fmaxf(tm1, sc[kb][3]);
            }
        }
        tm0 = fmaxf(tm0, __shfl_xor_sync(0xffffffffu, tm0, 1));
        tm0 = fmaxf(tm0, __shfl_xor_sync(0xffffffffu, tm0, 2));
        tm1 = fmaxf(tm1, __shfl_xor_sync(0xffffffffu, tm1, 1));
        tm1 = fmaxf(tm1, __shfl_xor_sync(0xffffffffu, tm1, 2));

        float mn0 = fmaxf(m0, tm0);
        float mn1 = fmaxf(m1, tm1);
        float alpha0 = __expf(m0 - mn0);
        float alpha1 = __expf(m1 - mn1);
        m0 = mn0; m1 = mn1;

        float sum0 = 0.f, sum1 = 0.f;
        if (full) {
#pragma unroll
            for (int kb = 0; kb < 8; kb++) {
                float p00 = __expf(sc[kb][0] - mn0);
                float p01 = __expf(sc[kb][1] - mn0);
                float p10 = __expf(sc[kb][2] - mn1);
                float p11 = __expf(sc[kb][3] - mn1);
                sc[kb][0] = p00; sc[kb][1] = p01; sc[kb][2] = p10; sc[kb][3] = p11;
                sum0 += p00 + p01;
                sum1 += p10 + p11;
            }
        } else {
#pragma unroll
            for (int kb = 0; kb < 8; kb++) {
                int c0 = j0 + kb * 8 + 2 * t;
                int c1 = c0 + 1;
                int d00 = r0 - c0, d01 = r0 - c1, d10 = r1 - c0, d11 = r1 - c1;
                float p00 = (d00 >= 0 && d00 < WINDOW) ? __expf(sc[kb][0] - mn0) : 0.f;
                float p01 = (d01 >= 0 && d01 < WINDOW) ? __expf(sc[kb][1] - mn0) : 0.f;
                float p10 = (d10 >= 0 && d10 < WINDOW) ? __expf(sc[kb][2] - mn1) : 0.f;
                float p11 = (d11 >= 0 && d11 < WINDOW) ? __expf(sc[kb][3] - mn1) : 0.f;
                sc[kb][0] = p00; sc[kb][1] = p01; sc[kb][2] = p10; sc[kb][3] = p11;
                sum0 += p00 + p01;
                sum1 += p10 + p11;
            }
        }
        sum0 += __shfl_xor_sync(0xffffffffu, sum0, 1);
        sum0 += __shfl_xor_sync(0xffffffffu, sum0, 2);
        sum1 += __shfl_xor_sync(0xffffffffu, sum1, 1);
        sum1 += __shfl_xor_sync(0xffffffffu, sum1, 2);
        l0 = l0 * alpha0 + sum0;
        l1 = l1 * alpha1 + sum1;

        // scale O accumulators
#pragma unroll
        for (int nb = 0; nb < 8; nb++) {
            oacc[nb][0] *= alpha0; oacc[nb][1] *= alpha0;
            oacc[nb][2] *= alpha1; oacc[nb][3] *= alpha1;
        }

        // ---- O += P @ V ----
        int srcA = (lane & ~3) | (t >> 1);
        int srcB = srcA + 2;
#pragma unroll
        for (int kb = 0; kb < 8; kb++) {
            // convert P (C layout, cols 2t/2t+1) -> A operand (cols t, t+4)
            float v0, v1;
            v0 = __shfl_sync(0xffffffffu, sc[kb][0], srcA);
            v1 = __shfl_sync(0xffffffffu, sc[kb][1], srcA);
            unsigned pa0 = __float_as_uint((t & 1) ? v1 : v0);
            v0 = __shfl_sync(0xffffffffu, sc[kb][2], srcA);
            v1 = __shfl_sync(0xffffffffu, sc[kb][3], srcA);
            unsigned pa1 = __float_as_uint((t & 1) ? v1 : v0);
            v0 = __shfl_sync(0xffffffffu, sc[kb][0], srcB);
            v1 = __shfl_sync(0xffffffffu, sc[kb][1], srcB);
            unsigned pa2 = __float_as_uint((t & 1) ? v1 : v0);
            v0 = __shfl_sync(0xffffffffu, sc[kb][2], srcB);
            v1 = __shfl_sync(0xffffffffu, sc[kb][3], srcB);
            unsigned pa3 = __float_as_uint((t & 1) ? v1 : v0);

            const float* vrow0 = Vs + (kb * 8 + t) * VLD;
            const float* vrow1 = Vs + (kb * 8 + t + 4) * VLD;
#pragma unroll
            for (int nb = 0; nb < 8; nb++) {
                unsigned b0 = __float_as_uint(vrow0[nb * 8 + g]);
                unsigned b1 = __float_as_uint(vrow1[nb * 8 + g]);
                mma_tf32(oacc[nb][0], oacc[nb][1], oacc[nb][2], oacc[nb][3],
                         pa0, pa1, pa2, pa3, b0, b1);
            }
        }
        __syncthreads();
    }

    // ---- write normalized output ----
    float rl0 = 1.f / l0;
    float rl1 = 1.f / l1;
#pragma unroll
    for (int nb = 0; nb < 8; nb++) {
        float2 o0 = make_float2(oacc[nb][0] * rl0, oacc[nb][1] * rl0);
        float2 o1 = make_float2(oacc[nb][2] * rl1, oacc[nb][3] * rl1);
        *(float2*)(o + base + (long long)r0 * DMODEL + nb * 8 + 2 * t) = o0;
        *(float2*)(o + base + (long long)r1 * DMODEL + nb * 8 + 2 * t) = o1;
    }
}

// ---------------------------------------------------------------------------
// Gating
// ---------------------------------------------------------------------------
__global__ void gate_kernel(const float* __restrict__ xn2,
                            const float* __restrict__ gw,
                            float* __restrict__ wte,
                            float* __restrict__ phis)
{
    int tok  = (blockIdx.x * blockDim.x + threadIdx.x) >> 5;
    int lane = threadIdx.x & 31;
    if (tok >= T_TOK) return;
    const float* xr = xn2 + (long long)tok * DMODEL;
    float acc[NE];
#pragma unroll
    for (int e = 0; e < NE; e++) acc[e] = 0.f;
    for (int d = lane; d < DMODEL; d += 32) {
        float xv = xr[d];
        const float* g = gw + d * NE;
#pragma unroll
        for (int e = 0; e < NE; e++) acc[e] = fmaf(xv, g[e], acc[e]);
    }
#pragma unroll
    for (int e = 0; e < NE; e++)
#pragma unroll
        for (int off = 16; off; off >>= 1)
            acc[e] += __shfl_xor_sync(0xffffffffu, acc[e], off);

    if (lane == 0) {
        float mx = acc[0];
#pragma unroll
        for (int e = 1; e < NE; e++) mx = fmaxf(mx, acc[e]);
        float p[NE], s = 0.f;
#pragma unroll
        for (int e = 0; e < NE; e++) { p[e] = expf(acc[e] - mx); s += p[e]; }
#pragma unroll
        for (int e = 0; e < NE; e++) p[e] /= s;
        int i1 = 0;
#pragma unroll
        for (int e = 1; e < NE; e++) if (p[e] > p[i1]) i1 = e;
        int i2 = -1;
#pragma unroll
        for (int e = 0; e < NE; e++)
            if (e != i1 && (i2 < 0 || p[e] > p[i2])) i2 = e;
#pragma unroll
        for (int e = 0; e < NE; e++)
            wte[(long long)tok * NE + e] = (e == i1) ? p[i1] : (e == i2) ? p[i2] : 0.f;
#pragma unroll
        for (int e = 0; e < NE; e++) atomicAdd(&phis[e], p[e]);
    }
}

// ---------------------------------------------------------------------------
// Per-expert top-CAP selection (bitonic, stable)
// ---------------------------------------------------------------------------
__global__ void expert_topk_kernel(const float* __restrict__ wte,
                                   int* __restrict__ capidx,
                                   float* __restrict__ capval)
{
    __shared__ float sv[T_TOK];
    __shared__ int   si[T_TOK];
    int e = blockIdx.x;
    for (int i = threadIdx.x; i < T_TOK; i += 1024) {
        sv[i] = wte[(long long)i * NE + e];
        si[i] = i;
    }
    __syncthreads();
    for (int kk = 2; kk <= T_TOK; kk <<= 1) {
        for (int j = kk >> 1; j > 0; j >>= 1) {
            for (int i = threadIdx.x; i < T_TOK; i += 1024) {
                int l = i ^ j;
                if (l > i) {
                    bool dir = ((i & kk) == 0);
                    float vi = sv[i], vl = sv[l];
                    int   xi = si[i], xl = si[l];
                    bool before = (vi > vl) || (vi == vl && xi < xl);
                    if (before != dir) {
                        sv[i] = vl; sv[l] = vi;
                        si[i] = xl; si[l] = xi;
                    }
                }
            }
            __syncthreads();
        }
    }
    for (int i = threadIdx.x; i < CAP; i += 1024) {
        capidx[e * CAP + i] = si[i];
        capval[e * CAP + i] = sv[i];
    }
}

// ---------------------------------------------------------------------------
// SwiGLU (vectorized)
// ---------------------------------------------------------------------------
__global__ void act_kernel(const float* __restrict__ hid, float* __restrict__ act)
{
    long long idx4 = (long long)blockIdx.x * blockDim.x + threadIdx.x;
    if (idx4 >= (long long)NE * CAP * DFF / 4) return;
    int f4 = (int)(idx4 % (DFF / 4));
    long long row = idx4 / (DFF / 4);
    const float4 h1 = *(const float4*)(hid + row * (2 * DFF) + f4 * 4);
    const float4 h2 = *(const float4*)(hid + row * (2 * DFF) + DFF + f4 * 4);
    float4 r;
    r.x = h1.x * (h2.x / (1.f + __expf(-h2.x)));
    r.y = h1.y * (h2.y / (1.f + __expf(-h2.y)));
    r.z = h1.z * (h2.z / (1.f + __expf(-h2.z)));
    r.w = h1.w * (h2.w / (1.f + __expf(-h2.w)));
    *(float4*)(act + row * DFF + f4 * 4) = r;
}

// ---------------------------------------------------------------------------
// Utility
// ---------------------------------------------------------------------------
__global__ void zero_phis_kernel(float* __restrict__ phis)
{
    if (threadIdx.x < NE) phis[threadIdx.x] = 0.f;
}

__global__ void aux_kernel(const float* __restrict__ phis, float* __restrict__ out, int out_size)
{
    if (out_size > OUT_MAIN) {
        float s = 0.f;
#pragma unroll
        for (int e = 0; e < NE; e++) {
            float pm = phis[e] / (float)T_TOK;
            s += pm * pm;
        }
        out[OUT_MAIN] = (float)NE * s;
    }
}

// ---------------------------------------------------------------------------
// Launch
// ---------------------------------------------------------------------------
extern "C" void kernel_launch(void* const* d_in, const int* in_sizes, int n_in,
                              void* d_out, int out_size)
{
    const float* x   = (const float*)d_in[0];
    const float* wq  = (const float*)d_in[1];
    const float* wk  = (const float*)d_in[2];
    const float* wv  = (const float*)d_in[3];
    const float* wo  = (const float*)d_in[4];
    const float* n1w = (const float*)d_in[5];
    const float* n2w = (const float*)d_in[6];
    const float* gw  = (const float*)d_in[7];
    const float* w1  = (const float*)d_in[8];
    const float* w2  = (const float*)d_in[9];
    float* out = (float*)d_out;

    float *xn, *qb, *kb, *vb, *ao, *hb, *xn2, *wte, *hid, *act, *capv, *phis;
    int* capi;
    cudaGetSymbolAddress((void**)&xn,  g_xn);
    cudaGetSymbolAddress((void**)&qb,  g_q);
    cudaGetSymbolAddress((void**)&kb,  g_k);
    cudaGetSymbolAddress((void**)&vb,  g_v);
    cudaGetSymbolAddress((void**)&ao,  g_ao);
    cudaGetSymbolAddress((void**)&hb,  g_h);
    cudaGetSymbolAddress((void**)&xn2, g_xn2);
    cudaGetSymbolAddress((void**)&wte, g_wte);
    cudaGetSymbolAddress((void**)&hid, g_hid);
    cudaGetSymbolAddress((void**)&act, g_act);
    cudaGetSymbolAddress((void**)&capi, g_capidx);
    cudaGetSymbolAddress((void**)&capv, g_capval);
    cudaGetSymbolAddress((void**)&phis, g_phis);

    static int attr_done = 0;
    if (!attr_done) {
        cudaFuncSetAttribute(wgemm_kernel<0>, cudaFuncAttributeMaxDynamicSharedMemorySize, GEMM_SMEM_BYTES);
        cudaFuncSetAttribute(wgemm_kernel<1>, cudaFuncAttributeMaxDynamicSharedMemorySize, GEMM_SMEM_BYTES);
        cudaFuncSetAttribute(wgemm_kernel<2>, cudaFuncAttributeMaxDynamicSharedMemorySize, GEMM_SMEM_BYTES);
        cudaFuncSetAttribute(wgemm_kernel<3>, cudaFuncAttributeMaxDynamicSharedMemorySize, GEMM_SMEM_BYTES);
        cudaFuncSetAttribute(attn_kernel, cudaFuncAttributeMaxDynamicSharedMemorySize, ATT_SMEM_BYTES);
        attr_done = 1;
    }

    // ---- sublayer 1 ----
    rmsnorm_kernel<<<T_TOK, 256>>>(x, n1w, xn);

    // Fused QKV: grid.x = 3 weights x 8 col-blocks, grid.y = 4096/256
    wgemm_kernel<3><<<dim3(24, T_TOK / BM, 1), 256, GEMM_SMEM_BYTES>>>(
        xn, wq, wk, wv, qb, kb, vb, nullptr, nullptr, nullptr, nullptr,
        DMODEL, DMODEL, 0, 0, 0, 0);

    rope_kernel<<<(T_TOK * NH * 32 + 255) / 256, 256>>>(qb, kb);

    attn_kernel<<<dim3(SEQ / 128, NH, NB), 256, ATT_SMEM_BYTES>>>(qb, kb, vb, ao);

    // O-proj + residual, dual-stored to h and out
    wgemm_kernel<1><<<dim3(DMODEL / BN, T_TOK / BM, 1), 256, GEMM_SMEM_BYTES>>>(
        ao, wo, nullptr, nullptr, hb, out, nullptr, x, nullptr, nullptr, nullptr,
        DMODEL, DMODEL, 0, 0, 0, 0);

    // ---- sublayer 2: MoE ----
    rmsnorm_kernel<<<T_TOK, 256>>>(hb, n2w, xn2);

    zero_phis_kernel<<<1, 32>>>(phis);
    gate_kernel<<<(T_TOK * 32) / 256, 256>>>(xn2, gw, wte, phis);
    expert_topk_kernel<<<NE, 1024>>>(wte, capi, capv);

    // hidden[e] = xn2[capidx[e]] @ w1[e]   (M=512, N=4096, K=1024)
    wgemm_kernel<0><<<dim3((2 * DFF) / BN, CAP / BM, NE), 256, GEMM_SMEM_BYTES>>>(
        xn2, w1, nullptr, nullptr, hid, nullptr, nullptr, nullptr, capi, nullptr, nullptr,
        2 * DFF, DMODEL,
        0, (long long)DMODEL * 2 * DFF, (long long)CAP * 2 * DFF, CAP);

    act_kernel<<<(NE * CAP * DFF / 4 + 255) / 256, 256>>>(hid, act);

    // out[capidx[e][c]] += (act[e] @ w2[e])[c] * capval[e][c]  (M=512,N=1024,K=2048)
    wgemm_kernel<2><<<dim3(DMODEL / BN, CAP / BM, NE), 256, GEMM_SMEM_BYTES>>>(
        act, w2, nullptr, nullptr, out, nullptr, nullptr, nullptr, nullptr, capi, capv,
        DMODEL, DFF,
        (long long)CAP * DFF, (long long)DFF * DMODEL, 0, CAP);

    aux_kernel<<<1, 1>>>(phis, out, out_size);

    (void)in_sizes; (void)n_in;
}

// round 17
// speedup vs baseline: 2.9705x; 1.3606x over previous
#include <cuda_runtime.h>
#include <cuda_bf16.h>
#include <cstdint>
#include <math.h>
#include <mma.h>

using namespace nvcuda;

// ---------------------------------------------------------------------------
// Problem constants
// ---------------------------------------------------------------------------
#define NB     2
#define SEQ    2048
#define T_TOK  4096
#define DMODEL 1024
#define NH     16
#define HD     64
#define WINDOW 1024
#define NE     8
#define DFF    2048
#define CAP    512
#define OUT_MAIN (T_TOK * DMODEL)

// ---------------------------------------------------------------------------
// Scratch
// ---------------------------------------------------------------------------
__device__ float g_xn  [T_TOK * DMODEL];
__device__ float g_q   [T_TOK * DMODEL];
__device__ float g_k   [T_TOK * DMODEL];
__device__ float g_v   [T_TOK * DMODEL];
__device__ float g_ao  [T_TOK * DMODEL];
__device__ float g_h   [T_TOK * DMODEL];
__device__ float g_xn2 [T_TOK * DMODEL];
__device__ float g_wte [T_TOK * NE];
__device__ float g_hid [NE * CAP * 2 * DFF];
__device__ int   g_capidx[NE * CAP];
__device__ float g_capval[NE * CAP];
__device__ float g_phis[NE];
__device__ __nv_bfloat16 g_xn2b[T_TOK * DMODEL];        // 8 MB
__device__ __nv_bfloat16 g_w1b [NE * DMODEL * 2 * DFF]; // [e][K][N] bf16, 64 MB
__device__ __nv_bfloat16 g_w2b [NE * DFF * DMODEL];     // [e][K][N] bf16, 32 MB
__device__ __nv_bfloat16 g_actb[NE * CAP * DFF];        // 16 MB

// ---------------------------------------------------------------------------
// cp.async helpers
// ---------------------------------------------------------------------------
__device__ __forceinline__ void cp16(void* dst, const void* src)
{
    unsigned int d = (unsigned int)__cvta_generic_to_shared(dst);
    asm volatile("cp.async.cg.shared.global [%0], [%1], 16;\n" :: "r"(d), "l"(src));
}
__device__ __forceinline__ void cp_commit() { asm volatile("cp.async.commit_group;\n"); }
__device__ __forceinline__ void cp_wait2()  { asm volatile("cp.async.wait_group 2;\n"); }
__device__ __forceinline__ void cp_wait1()  { asm volatile("cp.async.wait_group 1;\n"); }
__device__ __forceinline__ void cp_wait0()  { asm volatile("cp.async.wait_group 0;\n"); }

// mma.sync m16n8k8 tf32 (truncated)
__device__ __forceinline__ void mma_tf32(float& d0, float& d1, float& d2, float& d3,
                                         unsigned a0, unsigned a1, unsigned a2, unsigned a3,
                                         unsigned b0, unsigned b1)
{
    asm volatile(
        "mma.sync.aligned.m16n8k8.row.col.f32.tf32.tf32.f32 "
        "{%0,%1,%2,%3},{%4,%5,%6,%7},{%8,%9},{%0,%1,%2,%3};\n"
        : "+f"(d0), "+f"(d1), "+f"(d2), "+f"(d3)
        : "r"(a0), "r"(a1), "r"(a2), "r"(a3), "r"(b0), "r"(b1));
}

// ---------------------------------------------------------------------------
// RMSNorm
// ---------------------------------------------------------------------------
__global__ void rmsnorm_kernel(const float* __restrict__ x,
                               const float* __restrict__ w,
                               float* __restrict__ o)
{
    int row = blockIdx.x;
    const float* xr = x + (long long)row * DMODEL;
    float vals[4];
    float ss = 0.f;
#pragma unroll
    for (int t = 0; t < 4; t++) {
        float v = xr[threadIdx.x + t * 256];
        vals[t] = v;
        ss += v * v;
    }
    __shared__ float red[8];
#pragma unroll
    for (int off = 16; off; off >>= 1)
        ss += __shfl_xor_sync(0xffffffffu, ss, off);
    if ((threadIdx.x & 31) == 0) red[threadIdx.x >> 5] = ss;
    __syncthreads();
    if (threadIdx.x == 0) {
        float s = 0.f;
#pragma unroll
        for (int i = 0; i < 8; i++) s += red[i];
        red[0] = s;
    }
    __syncthreads();
    float rinv = 1.f / sqrtf(red[0] / (float)DMODEL + 1e-6f);
    float* orow = o + (long long)row * DMODEL;
#pragma unroll
    for (int t = 0; t < 4; t++) {
        int d = threadIdx.x + t * 256;
        orow[d] = vals[t] * rinv * w[d];
    }
}

// ---------------------------------------------------------------------------
// WMMA tf32 GEMM (3-stage) -- QKV (EPI3) and O-proj (EPI1).
// ---------------------------------------------------------------------------
#define BM 256
#define BN 128
#define ALD 36
#define BLD 132
#define STAGE_F (BM * ALD + 32 * BLD)
#define GEMM_SMEM_BYTES (3 * STAGE_F * 4)

template<int EPI>
__global__ __launch_bounds__(256)
void wgemm_kernel(const float* __restrict__ A,
                  const float* __restrict__ B0,
                  const float* __restrict__ B1,
                  const float* __restrict__ B2,
                  float* __restrict__ C0,
                  float* __restrict__ C1,
                  float* __restrict__ C2,
                  const float* __restrict__ resid,
                  int N, int K)
{
    extern __shared__ float sm[];

    const float* B_;
    float* C_;
    int colBase;
    if (EPI == 3) {
        int sel = blockIdx.x >> 3;
        colBase = (blockIdx.x & 7) * BN;
        B_ = (sel == 0) ? B0 : (sel == 1) ? B1 : B2;
        C_ = (sel == 0) ? C0 : (sel == 1) ? C1 : C2;
    } else {
        colBase = blockIdx.x * BN;
        B_ = B0;
        C_ = C0;
    }

    int tid = threadIdx.x;
    int w   = tid >> 5;
    int wr  = w >> 1;
    int wc  = w & 1;
    int rowBase = blockIdx.y * BM;

    wmma::fragment<wmma::accumulator, 16, 16, 8, float> acc[4][4];
#pragma unroll
    for (int i = 0; i < 4; i++)
#pragma unroll
        for (int j = 0; j < 4; j++) wmma::fill_fragment(acc[i][j], 0.f);

    int nIt = K >> 5;

    auto load_tile = [&](int it, int buf) {
        float* As = sm + buf * STAGE_F;
        float* Bs = As + BM * ALD;
        int k0 = it << 5;
#pragma unroll
        for (int t = 0; t < 8; t++) {
            int g  = tid + t * 256;
            int m  = g >> 3;
            int kq = (g & 7) << 2;
            cp16(As + m * ALD + kq, A + (long long)(rowBase + m) * K + k0 + kq);
        }
#pragma unroll
        for (int t = 0; t < 4; t++) {
            int g  = tid + t * 256;
            int kk = g >> 5;
            int nq = (g & 31) << 2;
            cp16(Bs + kk * BLD + nq, B_ + (long long)(k0 + kk) * N + colBase + nq);
        }
        cp_commit();
    };

    load_tile(0, 0);
    if (nIt > 1) load_tile(1, 1);
    int stage = 0;
    for (int it = 0; it < nIt; it++) {
        if (it + 2 < nIt) { load_tile(it + 2, (stage + 2) % 3); cp_wait2(); }
        else if (it + 1 < nIt) cp_wait1();
        else cp_wait0();
        __syncthreads();

        float* As = sm + stage * STAGE_F;
        float* Bs = As + BM * ALD;
#pragma unroll
        for (int ks = 0; ks < 4; ks++) {
            wmma::fragment<wmma::matrix_a, 16, 16, 8, wmma::precision::tf32, wmma::row_major> a[4];
            wmma::fragment<wmma::matrix_b, 16, 16, 8, wmma::precision::tf32, wmma::row_major> b[4];
#pragma unroll
            for (int i = 0; i < 4; i++)
                wmma::load_matrix_sync(a[i], As + (wr * 64 + i * 16) * ALD + ks * 8, ALD);
#pragma unroll
            for (int j = 0; j < 4; j++)
                wmma::load_matrix_sync(b[j], Bs + (ks * 8) * BLD + wc * 64 + j * 16, BLD);
#pragma unroll
            for (int i = 0; i < 4; i++)
#pragma unroll
                for (int j = 0; j < 4; j++)
                    wmma::mma_sync(acc[i][j], a[i], b[j], acc[i][j]);
        }
        __syncthreads();
        stage = (stage + 1) % 3;
    }

    if (EPI == 3) {
#pragma unroll
        for (int i = 0; i < 4; i++)
#pragma unroll
            for (int j = 0; j < 4; j++) {
                long long m = rowBase + wr * 64 + i * 16;
                long long n = colBase + wc * 64 + j * 16;
                wmma::store_matrix_sync(C_ + m * N + n, acc[i][j], N, wmma::mem_row_major);
            }
    } else {  // EPI 1: += resid, dual store
        float* Csm = sm;
#pragma unroll
        for (int half = 0; half < 2; half++) {
            if ((wr >> 1) == half) {
#pragma unroll
                for (int i = 0; i < 4; i++)
#pragma unroll
                    for (int j = 0; j < 4; j++)
                        wmma::store_matrix_sync(Csm + ((wr & 1) * 64 + i * 16) * BLD + wc * 64 + j * 16,
                                                acc[i][j], BLD, wmma::mem_row_major);
            }
            __syncthreads();
#pragma unroll
            for (int t = 0; t < 64; t++) {
                int idx = tid + t * 256;
                int m = idx >> 7, n = idx & 127;
                long long gm = (long long)(rowBase + half * 128 + m) * N + colBase + n;
                float v = Csm[m * BLD + n] + resid[gm];
                C_[gm] = v;
                if (C1) C1[gm] = v;
            }
            __syncthreads();
        }
    }
}

// ---------------------------------------------------------------------------
// WMMA bf16 GEMM (3-stage) for MoE: C[M,N] = A_bf16 @ B_bf16[K,N]
// Tile 256x128, BK=32, 8 warps each 64x64, m16n16k16 bf16 fragments.
// EPI 0: gather A rows via idx, plain store. EPI 2: scatter atomicAdd*scale.
// ---------------------------------------------------------------------------
#define ALDH 40    // bf16 elems per A row (32 + 8 pad)
#define BLDH 136   // bf16 elems per B row (128 + 8 pad)
#define STAGE_H (BM * ALDH + 32 * BLDH)              // 14592 bf16
#define HGEMM_SMEM_BYTES (3 * STAGE_H * 2)           // 87552 B

template<int EPI>
__global__ __launch_bounds__(256)
void hgemm_kernel(const __nv_bfloat16* __restrict__ A,    // [*, K] row-major
                  const __nv_bfloat16* __restrict__ Bt,   // [e][K][N]
                  float* __restrict__ C,
                  const int* __restrict__ rowIdx,         // EPI0: gather, EPI2: scatter
                  const float* __restrict__ rowScale,     // EPI2
                  int N, int K)
{
    extern __shared__ __nv_bfloat16 smh[];
    __shared__ int   idx_sm[BM];
    __shared__ float scl_sm[BM];

    int e = blockIdx.z;
    int colBase = blockIdx.x * BN;
    int rowBase = blockIdx.y * BM;
    int tid = threadIdx.x;
    int w   = tid >> 5;
    int wr  = w >> 1;
    int wc  = w & 1;

    const __nv_bfloat16* B_ = Bt + (long long)e * K * N;

    {
        int r = e * CAP + rowBase + tid;
        idx_sm[tid] = rowIdx[r];
        if (EPI == 2) scl_sm[tid] = rowScale[r];
    }
    __syncthreads();

    wmma::fragment<wmma::accumulator, 16, 16, 16, float> acc[4][4];
#pragma unroll
    for (int i = 0; i < 4; i++)
#pragma unroll
        for (int j = 0; j < 4; j++) wmma::fill_fragment(acc[i][j], 0.f);

    int nIt = K >> 5;

    auto load_tile = [&](int it, int buf) {
        __nv_bfloat16* As = smh + buf * STAGE_H;
        __nv_bfloat16* Bs = As + BM * ALDH;
        int k0 = it << 5;
        // A: 256 rows x 32 k  (8 bf16 per cp16) -> 1024 cp16
#pragma unroll
        for (int t = 0; t < 4; t++) {
            int g  = tid + t * 256;
            int m  = g >> 2;
            int kq = (g & 3) << 3;
            long long arow = (EPI == 0) ? (long long)idx_sm[m]
                                        : (long long)(e * CAP + rowBase + m);
            cp16(As + m * ALDH + kq, A + arow * K + k0 + kq);
        }
        // B: 32 rows x 128 n -> 512 cp16
#pragma unroll
        for (int t = 0; t < 2; t++) {
            int g  = tid + t * 256;
            int kk = g >> 4;
            int nq = (g & 15) << 3;
            cp16(Bs + kk * BLDH + nq, B_ + (long long)(k0 + kk) * N + colBase + nq);
        }
        cp_commit();
    };

    load_tile(0, 0);
    if (nIt > 1) load_tile(1, 1);
    int stage = 0;
    for (int it = 0; it < nIt; it++) {
        if (it + 2 < nIt) { load_tile(it + 2, (stage + 2) % 3); cp_wait2(); }
        else if (it + 1 < nIt) cp_wait1();
        else cp_wait0();
        __syncthreads();

        __nv_bfloat16* As = smh + stage * STAGE_H;
        __nv_bfloat16* Bs = As + BM * ALDH;
#pragma unroll
        for (int ks = 0; ks < 2; ks++) {
            wmma::fragment<wmma::matrix_a, 16, 16, 16, __nv_bfloat16, wmma::row_major> a[4];
            wmma::fragment<wmma::matrix_b, 16, 16, 16, __nv_bfloat16, wmma::row_major> b[4];
#pragma unroll
            for (int i = 0; i < 4; i++)
                wmma::load_matrix_sync(a[i], As + (wr * 64 + i * 16) * ALDH + ks * 16, ALDH);
#pragma unroll
            for (int j = 0; j < 4; j++)
                wmma::load_matrix_sync(b[j], Bs + (ks * 16) * BLDH + wc * 64 + j * 16, BLDH);
#pragma unroll
            for (int i = 0; i < 4; i++)
#pragma unroll
                for (int j = 0; j < 4; j++)
                    wmma::mma_sync(acc[i][j], a[i], b[j], acc[i][j]);
        }
        __syncthreads();
        stage = (stage + 1) % 3;
    }

    if (EPI == 0) {
#pragma unroll
        for (int i = 0; i < 4; i++)
#pragma unroll
            for (int j = 0; j < 4; j++) {
                long long m = (long long)(e * CAP) + rowBase + wr * 64 + i * 16;
                long long n = colBase + wc * 64 + j * 16;
                wmma::store_matrix_sync(C + m * N + n, acc[i][j], N, wmma::mem_row_major);
            }
    } else { // EPI 2: stage through smem, atomic scatter
        float* Csm = (float*)smh;   // 128 x BLD(132) floats, two halves
#pragma unroll
        for (int half = 0; half < 2; half++) {
            if ((wr >> 1) == half) {
#pragma unroll
                for (int i = 0; i < 4; i++)
#pragma unroll
                    for (int j = 0; j < 4; j++)
                        wmma::store_matrix_sync(Csm + ((wr & 1) * 64 + i * 16) * BLD + wc * 64 + j * 16,
                                                acc[i][j], BLD, wmma::mem_row_major);
            }
            __syncthreads();
#pragma unroll
            for (int t = 0; t < 64; t++) {
                int idx = tid + t * 256;
                int m = idx >> 7, n = idx & 127;
                int lr = half * 128 + m;
                atomicAdd(&C[(long long)idx_sm[lr] * N + colBase + n],
                          Csm[m * BLD + n] * scl_sm[lr]);
            }
            __syncthreads();
        }
    }
}

// ---------------------------------------------------------------------------
// Conversions
// ---------------------------------------------------------------------------
__global__ void f32_to_bf16_kernel(const float* __restrict__ src,
                                   __nv_bfloat16* __restrict__ dst, long long n4)
{
    long long i = (long long)blockIdx.x * blockDim.x + threadIdx.x;
    if (i >= n4) return;
    float4 v = ((const float4*)src)[i];
    __nv_bfloat162 p0 = __floats2bfloat162_rn(v.x, v.y);
    __nv_bfloat162 p1 = __floats2bfloat162_rn(v.z, v.w);
    uint2 u;
    u.x = *reinterpret_cast<unsigned*>(&p0);
    u.y = *reinterpret_cast<unsigned*>(&p1);
    ((uint2*)dst)[i] = u;
}

// ---------------------------------------------------------------------------
// RoPE
// ---------------------------------------------------------------------------
__global__ void rope_kernel(float* __restrict__ q, float* __restrict__ k)
{
    int idx = blockIdx.x * blockDim.x + threadIdx.x;
    if (idx >= T_TOK * NH * (HD / 2)) return;
    int j   = idx & 31;
    int hh  = (idx >> 5) & 15;
    int row = idx >> 9;
    int s   = row & (SEQ - 1);

    float inv = exp2f(-(float)j * 0.4152410118609203f);
    float ang = (float)s * inv;
    float c = cosf(ang), sn = sinf(ang);

    long long base = (long long)row * DMODEL + hh * HD;
    float q1 = q[base + j], q2 = q[base + j + 32];
    q[base + j]      = q1 * c - q2 * sn;
    q[base + j + 32] = q2 * c + q1 * sn;
    float k1 = k[base + j], k2 = k[base + j + 32];
    k[base + j]      = k1 * c - k2 * sn;
    k[base + j + 32] = k2 * c + k1 * sn;
}

// ---------------------------------------------------------------------------
// FA2 flash attention (tf32 mma.sync)
// ---------------------------------------------------------------------------
#define KLD 68
#define VLD 72
#define QLD 68
#define KV_STAGE_F (64 * KLD + 64 * VLD)
#define ATT_SMEM_BYTES (2 * KV_STAGE_F * 4)

__global__ __launch_bounds__(256, 2)
void attn_kernel(const float* __restrict__ q,
                 const float* __restrict__ k,
                 const float* __restrict__ v,
                 float* __restrict__ o)
{
    extern __shared__ float sm[];

    int qt = blockIdx.x, h = blockIdx.y, b = blockIdx.z;
    int i0 = qt * 128;
    int tid  = threadIdx.x;
    int w    = tid >> 5;
    int lane = tid & 31;
    int g    = lane >> 2;
    int t    = lane & 3;
    long long base = ((long long)b * SEQ) * DMODEL + h * HD;

    int r0base = i0 + w * 16;
    int r0 = r0base + g;
    int r1 = r0 + 8;

    unsigned qa[8][4];
    {
        float* Qs = sm;
#pragma unroll
        for (int u = 0; u < 2; u++) {
            int gidx = tid + u * 256;
            int row  = gidx >> 2;
            int c4   = (gidx & 3) << 4;
#pragma unroll
            for (int q4 = 0; q4 < 4; q4++) {
                float4 val = *(const float4*)(q + base + (long long)(i0 + row) * DMODEL + c4 + q4 * 4);
                val.x *= 0.125f; val.y *= 0.125f; val.z *= 0.125f; val.w *= 0.125f;
                *(float4*)(Qs + row * QLD + c4 + q4 * 4) = val;
            }
        }
        __syncthreads();
        int lr0 = w * 16 + g, lr1 = lr0 + 8;
#pragma unroll
        for (int kc = 0; kc < 8; kc++) {
            qa[kc][0] = __float_as_uint(Qs[lr0 * QLD + kc * 8 + t]);
            qa[kc][1] = __float_as_uint(Qs[lr1 * QLD + kc * 8 + t]);
            qa[kc][2] = __float_as_uint(Qs[lr0 * QLD + kc * 8 + t + 4]);
            qa[kc][3] = __float_as_uint(Qs[lr1 * QLD + kc * 8 + t + 4]);
        }
        __syncthreads();
    }

    float m0 = -1e30f, m1 = -1e30f, l0 = 0.f, l1 = 0.f;
    float oacc[8][4];
#pragma unroll
    for (int nb = 0; nb < 8; nb++)
#pragma unroll
        for (int u = 0; u < 4; u++) oacc[nb][u] = 0.f;

    int jstart = i0 - (WINDOW - 1); if (jstart < 0) jstart = 0;
    int jt0 = jstart >> 6;
    int jt1 = (i0 + 127) >> 6;
    int nTiles = jt1 - jt0 + 1;

    auto loadKV = [&](int jt, int stage) {
        float* Ks = sm + stage * KV_STAGE_F;
        float* Vs = Ks + 64 * KLD;
        int j0 = jt << 6;
#pragma unroll
        for (int u = 0; u < 4; u++) {
            int gidx = tid + u * 256;
            int row  = gidx >> 4;
            int c4   = (gidx & 15) << 2;
            long long gp = base + (long long)(j0 + row) * DMODEL + c4;
            cp16(Ks + row * KLD + c4, k + gp);
            cp16(Vs + row * VLD + c4, v + gp);
        }
        cp_commit();
    };

    loadKV(jt0, 0);
    for (int it = 0; it < nTiles; it++) {
        int j0 = (jt0 + it) << 6;
        if (it + 1 < nTiles) { loadKV(jt0 + it + 1, (it + 1) & 1); cp_wait1(); }
        else cp_wait0();
        __syncthreads();

        float* Ks = sm + (it & 1) * KV_STAGE_F;
        float* Vs = Ks + 64 * KLD;

        float sc[8][4];
#pragma unroll
        for (int kb = 0; kb < 8; kb++) {
            float d0 = 0.f, d1 = 0.f, d2 = 0.f, d3 = 0.f;
            const float* krow = Ks + (kb * 8 + g) * KLD;
#pragma unroll
            for (int kc = 0; kc < 8; kc++) {
                unsigned b0 = __float_as_uint(krow[kc * 8 + t]);
                unsigned b1 = __float_as_uint(krow[kc * 8 + t + 4]);
                mma_tf32(d0, d1, d2, d3, qa[kc][0], qa[kc][1], qa[kc][2], qa[kc][3], b0, b1);
            }
            sc[kb][0] = d0; sc[kb][1] = d1; sc[kb][2] = d2; sc[kb][3] = d3;
        }

        bool full = (j0 + 63 <= r0base) && (j0 >= r0base + 16 - WINDOW);

        float tm0 = -1e30f, tm1 = -1e30f;
        if (full) {
#pragma unroll
            for (int kb = 0; kb < 8; kb++) {
                tm0 = fmaxf(tm0, fmaxf(sc[kb][0], sc[kb][1]));
                tm1 = fmaxf(tm1, fmaxf(sc[kb][2], sc[kb][3]));
            }
        } else {
#pragma unroll
            for (int kb = 0; kb < 8; kb++) {
                int c0 = j0 + kb * 8 + 2 * t;
                int c1 = c0 + 1;
                int d00 = r0 - c0, d01 = r0 - c1, d10 = r1 - c0, d11 = r1 - c1;
                if (d00 >= 0 && d00 < WINDOW) tm0 = fmaxf(tm0, sc[kb][0]);
                if (d01 >= 0 && d01 < WINDOW) tm0 = fmaxf(tm0, sc[kb][1]);
                if (d10 >= 0 && d10 < WINDOW) tm1 = fmaxf(tm1, sc[kb][2]);
                if (d11 >= 0 && d11 < WINDOW) tm1 = fmaxf(tm1, sc[kb][3]);
            }
        }
        tm0 = fmaxf(tm0, __shfl_xor_sync(0xffffffffu, tm0, 1));
        tm0 = fmaxf(tm0, __shfl_xor_sync(0xffffffffu, tm0, 2));
        tm1 = fmaxf(tm1, __shfl_xor_sync(0xffffffffu, tm1, 1));
        tm1 = fmaxf(tm1, __shfl_xor_sync(0xffffffffu, tm1, 2));

        float mn0 = fmaxf(m0, tm0);
        float mn1 = fmaxf(m1, tm1);
        float alpha0 = __expf(m0 - mn0);
        float alpha1 = __expf(m1 - mn1);
        m0 = mn0; m1 = mn1;

        float sum0 = 0.f, sum1 = 0.f;
        if (full) {
#pragma unroll
            for (int kb = 0; kb < 8; kb++) {
                float p00 = __expf(sc[kb][0] - mn0);
                float p01 = __expf(sc[kb][1] - mn0);
                float p10 = __expf(sc[kb][2] - mn1);
                float p11 = __expf(sc[kb][3] - mn1);
                sc[kb][0] = p00; sc[kb][1] = p01; sc[kb][2] = p10; sc[kb][3] = p11;
                sum0 += p00 + p01;
                sum1 += p10 + p11;
            }
        } else {
#pragma unroll
            for (int kb = 0; kb < 8; kb++) {
                int c0 = j0 + kb * 8 + 2 * t;
                int c1 = c0 + 1;
                int d00 = r0 - c0, d01 = r0 - c1, d10 = r1 - c0, d11 = r1 - c1;
                float p00 = (d00 >= 0 && d00 < WINDOW) ? __expf(sc[kb][0] - mn0) : 0.f;
                float p01 = (d01 >= 0 && d01 < WINDOW) ? __expf(sc[kb][1] - mn0) : 0.f;
                float p10 = (d10 >= 0 && d10 < WINDOW) ? __expf(sc[kb][2] - mn1) : 0.f;
                float p11 = (d11 >= 0 && d11 < WINDOW) ? __expf(sc[kb][3] - mn1) : 0.f;
                sc[kb][0] = p00; sc[kb][1] = p01; sc[kb][2] = p10; sc[kb][3] = p11;
                sum0 += p00 + p01;
                sum1 += p10 + p11;
            }
        }
        sum0 += __shfl_xor_sync(0xffffffffu, sum0, 1);
        sum0 += __shfl_xor_sync(0xffffffffu, sum0, 2);
        sum1 += __shfl_xor_sync(0xffffffffu, sum1, 1);
        sum1 += __shfl_xor_sync(0xffffffffu, sum1, 2);
        l0 = l0 * alpha0 + sum0;
        l1 = l1 * alpha1 + sum1;

#pragma unroll
        for (int nb = 0; nb < 8; nb++) {
            oacc[nb][0] *= alpha0; oacc[nb][1] *= alpha0;
            oacc[nb][2] *= alpha1; oacc[nb][3] *= alpha1;
        }

        int srcA = (lane & ~3) | (t >> 1);
        int srcB = srcA + 2;
#pragma unroll
        for (int kb = 0; kb < 8; kb++) {
            float v0, v1;
            v0 = __shfl_sync(0xffffffffu, sc[kb][0], srcA);
            v1 = __shfl_sync(0xffffffffu, sc[kb][1], srcA);
            unsigned pa0 = __float_as_uint((t & 1) ? v1 : v0);
            v0 = __shfl_sync(0xffffffffu, sc[kb][2], srcA);
            v1 = __shfl_sync(0xffffffffu, sc[kb][3], srcA);
            unsigned pa1 = __float_as_uint((t & 1) ? v1 : v0);
            v0 = __shfl_sync(0xffffffffu, sc[kb][0], srcB);
            v1 = __shfl_sync(0xffffffffu, sc[kb][1], srcB);
            unsigned pa2 = __float_as_uint((t & 1) ? v1 : v0);
            v0 = __shfl_sync(0xffffffffu, sc[kb][2], srcB);
            v1 = __shfl_sync(0xffffffffu, sc[kb][3], srcB);
            unsigned pa3 = __float_as_uint((t & 1) ? v1 : v0);

            const float* vrow0 = Vs + (kb * 8 + t) * VLD;
            const float* vrow1 = Vs + (kb * 8 + t + 4) * VLD;
#pragma unroll
            for (int nb = 0; nb < 8; nb++) {
                unsigned b0 = __float_as_uint(vrow0[nb * 8 + g]);
                unsigned b1 = __float_as_uint(vrow1[nb * 8 + g]);
                mma_tf32(oacc[nb][0], oacc[nb][1], oacc[nb][2], oacc[nb][3],
                         pa0, pa1, pa2, pa3, b0, b1);
            }
        }
        __syncthreads();
    }

    float rl0 = 1.f / l0;
    float rl1 = 1.f / l1;
#pragma unroll
    for (int nb = 0; nb < 8; nb++) {
        float2 o0 = make_float2(oacc[nb][0] * rl0, oacc[nb][1] * rl0);
        float2 o1 = make_float2(oacc[nb][2] * rl1, oacc[nb][3] * rl1);
        *(float2*)(o + base + (long long)r0 * DMODEL + nb * 8 + 2 * t) = o0;
        *(float2*)(o + base + (long long)r1 * DMODEL + nb * 8 + 2 * t) = o1;
    }
}

// ---------------------------------------------------------------------------
// Gating
// ---------------------------------------------------------------------------
__global__ void gate_kernel(const float* __restrict__ xn2,
                            const float* __restrict__ gw,
                            float* __restrict__ wte,
                            float* __restrict__ phis)
{
    int tok  = (blockIdx.x * blockDim.x + threadIdx.x) >> 5;
    int lane = threadIdx.x & 31;
    if (tok >= T_TOK) return;
    const float* xr = xn2 + (long long)tok * DMODEL;
    float acc[NE];
#pragma unroll
    for (int e = 0; e < NE; e++) acc[e] = 0.f;
    for (int d = lane; d < DMODEL; d += 32) {
        float xv = xr[d];
        const float* g = gw + d * NE;
#pragma unroll
        for (int e = 0; e < NE; e++) acc[e] = fmaf(xv, g[e], acc[e]);
    }
#pragma unroll
    for (int e = 0; e < NE; e++)
#pragma unroll
        for (int off = 16; off; off >>= 1)
            acc[e] += __shfl_xor_sync(0xffffffffu, acc[e], off);

    if (lane == 0) {
        float mx = acc[0];
#pragma unroll
        for (int e = 1; e < NE; e++) mx = fmaxf(mx, acc[e]);
        float p[NE], s = 0.f;
#pragma unroll
        for (int e = 0; e < NE; e++) { p[e] = expf(acc[e] - mx); s += p[e]; }
#pragma unroll
        for (int e = 0; e < NE; e++) p[e] /= s;
        int i1 = 0;
#pragma unroll
        for (int e = 1; e < NE; e++) if (p[e] > p[i1]) i1 = e;
        int i2 = -1;
#pragma unroll
        for (int e = 0; e < NE; e++)
            if (e != i1 && (i2 < 0 || p[e] > p[i2])) i2 = e;
#pragma unroll
        for (int e = 0; e < NE; e++)
            wte[(long long)tok * NE + e] = (e == i1) ? p[i1] : (e == i2) ? p[i2] : 0.f;
#pragma unroll
        for (int e = 0; e < NE; e++) atomicAdd(&phis[e], p[e]);
    }
}

// ---------------------------------------------------------------------------
// Per-expert top-CAP selection (bitonic, stable)
// ---------------------------------------------------------------------------
__global__ void expert_topk_kernel(const float* __restrict__ wte,
                                   int* __restrict__ capidx,
                                   float* __restrict__ capval)
{
    __shared__ float sv[T_TOK];
    __shared__ int   si[T_TOK];
    int e = blockIdx.x;
    for (int i = threadIdx.x; i < T_TOK; i += 1024) {
        sv[i] = wte[(long long)i * NE + e];
        si[i] = i;
    }
    __syncthreads();
    for (int kk = 2; kk <= T_TOK; kk <<= 1) {
        for (int j = kk >> 1; j > 0; j >>= 1) {
            for (int i = threadIdx.x; i < T_TOK; i += 1024) {
                int l = i ^ j;
                if (l > i) {
                    bool dir = ((i & kk) == 0);
                    float vi = sv[i], vl = sv[l];
                    int   xi = si[i], xl = si[l];
                    bool before = (vi > vl) || (vi == vl && xi < xl);
                    if (before != dir) {
                        sv[i] = vl; sv[l] = vi;
                        si[i] = xl; si[l] = xi;
                    }
                }
            }
            __syncthreads();
        }
    }
    for (int i = threadIdx.x; i < CAP; i += 1024) {
        capidx[e * CAP + i] = si[i];
        capval[e * CAP + i] = sv[i];
    }
}

// ---------------------------------------------------------------------------
// SwiGLU -> bf16 out
// ---------------------------------------------------------------------------
__global__ void act_kernel(const float* __restrict__ hid, __nv_bfloat16* __restrict__ actb)
{
    long long idx4 = (long long)blockIdx.x * blockDim.x + threadIdx.x;
    if (idx4 >= (long long)NE * CAP * DFF / 4) return;
    int f4 = (int)(idx4 % (DFF / 4));
    long long row = idx4 / (DFF / 4);
    const float4 h1 = *(const float4*)(hid + row * (2 * DFF) + f4 * 4);
    const float4 h2 = *(const float4*)(hid + row * (2 * DFF) + DFF + f4 * 4);
    float4 r;
    r.x = h1.x * (h2.x / (1.f + __expf(-h2.x)));
    r.y = h1.y * (h2.y / (1.f + __expf(-h2.y)));
    r.z = h1.z * (h2.z / (1.f + __expf(-h2.z)));
    r.w = h1.w * (h2.w / (1.f + __expf(-h2.w)));
    __nv_bfloat162 p0 = __floats2bfloat162_rn(r.x, r.y);
    __nv_bfloat162 p1 = __floats2bfloat162_rn(r.z, r.w);
    uint2 u;
    u.x = *reinterpret_cast<unsigned*>(&p0);
    u.y = *reinterpret_cast<unsigned*>(&p1);
    *(uint2*)(actb + row * DFF + f4 * 4) = u;
}

// ---------------------------------------------------------------------------
// Utility
// ---------------------------------------------------------------------------
__global__ void zero_phis_kernel(float* __restrict__ phis)
{
    if (threadIdx.x < NE) phis[threadIdx.x] = 0.f;
}

__global__ void aux_kernel(const float* __restrict__ phis, float* __restrict__ out, int out_size)
{
    if (out_size > OUT_MAIN) {
        float s = 0.f;
#pragma unroll
        for (int e = 0; e < NE; e++) {
            float pm = phis[e] / (float)T_TOK;
            s += pm * pm;
        }
        out[OUT_MAIN] = (float)NE * s;
    }
}

// ---------------------------------------------------------------------------
// Launch
// ---------------------------------------------------------------------------
extern "C" void kernel_launch(void* const* d_in, const int* in_sizes, int n_in,
                              void* d_out, int out_size)
{
    const float* x   = (const float*)d_in[0];
    const float* wq  = (const float*)d_in[1];
    const float* wk  = (const float*)d_in[2];
    const float* wv  = (const float*)d_in[3];
    const float* wo  = (const float*)d_in[4];
    const float* n1w = (const float*)d_in[5];
    const float* n2w = (const float*)d_in[6];
    const float* gw  = (const float*)d_in[7];
    const float* w1  = (const float*)d_in[8];
    const float* w2  = (const float*)d_in[9];
    float* out = (float*)d_out;

    float *xn, *qb, *kb, *vb, *ao, *hb, *xn2, *wte, *hid, *capv, *phis;
    int* capi;
    __nv_bfloat16 *xn2b, *w1b, *w2b, *actb;
    cudaGetSymbolAddress((void**)&xn,   g_xn);
    cudaGetSymbolAddress((void**)&qb,   g_q);
    cudaGetSymbolAddress((void**)&kb,   g_k);
    cudaGetSymbolAddress((void**)&vb,   g_v);
    cudaGetSymbolAddress((void**)&ao,   g_ao);
    cudaGetSymbolAddress((void**)&hb,   g_h);
    cudaGetSymbolAddress((void**)&xn2,  g_xn2);
    cudaGetSymbolAddress((void**)&wte,  g_wte);
    cudaGetSymbolAddress((void**)&hid,  g_hid);
    cudaGetSymbolAddress((void**)&capi, g_capidx);
    cudaGetSymbolAddress((void**)&capv, g_capval);
    cudaGetSymbolAddress((void**)&phis, g_phis);
    cudaGetSymbolAddress((void**)&xn2b, g_xn2b);
    cudaGetSymbolAddress((void**)&w1b,  g_w1b);
    cudaGetSymbolAddress((void**)&w2b,  g_w2b);
    cudaGetSymbolAddress((void**)&actb, g_actb);

    static int attr_done = 0;
    if (!attr_done) {
        cudaFuncSetAttribute(wgemm_kernel<1>, cudaFuncAttributeMaxDynamicSharedMemorySize, GEMM_SMEM_BYTES);
        cudaFuncSetAttribute(wgemm_kernel<3>, cudaFuncAttributeMaxDynamicSharedMemorySize, GEMM_SMEM_BYTES);
        cudaFuncSetAttribute(attn_kernel, cudaFuncAttributeMaxDynamicSharedMemorySize, ATT_SMEM_BYTES);
        cudaFuncSetAttribute(hgemm_kernel<0>, cudaFuncAttributeMaxDynamicSharedMemorySize, HGEMM_SMEM_BYTES);
        cudaFuncSetAttribute(hgemm_kernel<2>, cudaFuncAttributeMaxDynamicSharedMemorySize, HGEMM_SMEM_BYTES);
        attr_done = 1;
    }

    // ---- weight conversions (elementwise, layout preserved) ----
    f32_to_bf16_kernel<<<((long long)NE * DMODEL * 2 * DFF / 4 + 255) / 256, 256>>>(
        w1, w1b, (long long)NE * DMODEL * 2 * DFF / 4);
    f32_to_bf16_kernel<<<((long long)NE * DFF * DMODEL / 4 + 255) / 256, 256>>>(
        w2, w2b, (long long)NE * DFF * DMODEL / 4);

    // ---- sublayer 1 ----
    rmsnorm_kernel<<<T_TOK, 256>>>(x, n1w, xn);

    wgemm_kernel<3><<<dim3(24, T_TOK / BM, 1), 256, GEMM_SMEM_BYTES>>>(
        xn, wq, wk, wv, qb, kb, vb, nullptr, DMODEL, DMODEL);

    rope_kernel<<<(T_TOK * NH * 32 + 255) / 256, 256>>>(qb, kb);

    attn_kernel<<<dim3(SEQ / 128, NH, NB), 256, ATT_SMEM_BYTES>>>(qb, kb, vb, ao);

    wgemm_kernel<1><<<dim3(DMODEL / BN, T_TOK / BM, 1), 256, GEMM_SMEM_BYTES>>>(
        ao, wo, nullptr, nullptr, hb, out, nullptr, x, DMODEL, DMODEL);

    // ---- sublayer 2: MoE ----
    rmsnorm_kernel<<<T_TOK, 256>>>(hb, n2w, xn2);
    f32_to_bf16_kernel<<<(T_TOK * DMODEL / 4 + 255) / 256, 256>>>(xn2, xn2b, T_TOK * DMODEL / 4);

    zero_phis_kernel<<<1, 32>>>(phis);
    gate_kernel<<<(T_TOK * 32) / 256, 256>>>(xn2, gw, wte, phis);
    expert_topk_kernel<<<NE, 1024>>>(wte, capi, capv);

    // hidden[e] = gather(xn2b) @ w1b[e]   (bf16 HMMA; M=512,N=4096,K=1024)
    hgemm_kernel<0><<<dim3((2 * DFF) / BN, CAP / BM, NE), 256, HGEMM_SMEM_BYTES>>>(
        xn2b, w1b, hid, capi, nullptr, 2 * DFF, DMODEL);

    act_kernel<<<(NE * CAP * DFF / 4 + 255) / 256, 256>>>(hid, actb);

    // out[capidx] += (actb[e] @ w2b[e]) * capval   (bf16 HMMA + scatter)
    hgemm_kernel<2><<<dim3(DMODEL / BN, CAP / BM, NE), 256, HGEMM_SMEM_BYTES>>>(
        actb, w2b, out, capi, capv, DMODEL, DFF);

    aux_kernel<<<1, 1>>>(phis, out, out_size);

    (void)in_sizes; (void)n_in;
}